// round 14
// baseline (speedup 1.0000x reference)
#include <cuda_runtime.h>
#include <cuda_bf16.h>
#include <cstdint>

#define BB 2
#define TT 2048
#define DD 1024
#define HH 16
#define HD 64
#define M_ROWS (BB*TT)   // 4096

// ---------------------------------------------------------------------------
// Device scratch (allocation-free). Fragment-image layouts; B-side PAIRED.
// ---------------------------------------------------------------------------
__device__ uint32_t g_qfh[BB*HH*16*4096];
__device__ uint32_t g_qfl[BB*HH*16*4096];
__device__ uint32_t g_kfh[BB*HH*32*2048];
__device__ uint32_t g_kfl[BB*HH*32*2048];
__device__ uint32_t g_vfh[BB*HH*32*2048];
__device__ uint32_t g_vfl[BB*HH*32*2048];
__device__ uint32_t g_xh[M_ROWS*512];
__device__ uint32_t g_xl[M_ROWS*512];
__device__ uint32_t g_wqh[DD*512], g_wql[DD*512];
__device__ uint32_t g_wkh[DD*512], g_wkl[DD*512];
__device__ uint32_t g_wvh[DD*512], g_wvl[DD*512];
__device__ uint32_t g_woh[DD*512], g_wol[DD*512];
__device__ uint32_t g_aoh[M_ROWS*512];
__device__ uint32_t g_aol[M_ROWS*512];
__device__ int g_flags[32];   // per (b*16 + qi) attention-completion counters

// ---------------------------------------------------------------------------
// helpers
// ---------------------------------------------------------------------------
__device__ __forceinline__ uint32_t smem_u32(const void* p) {
    return (uint32_t)__cvta_generic_to_shared(p);
}

#define CP16(d, s) asm volatile("cp.async.cg.shared.global [%0], [%1], 16;" \
                                :: "r"(d), "l"(s) : "memory")

__device__ __forceinline__ void mma16816(float* c, const uint32_t* a, const uint32_t* b) {
    asm volatile(
        "mma.sync.aligned.m16n8k16.row.col.f32.bf16.bf16.f32 "
        "{%0,%1,%2,%3}, {%4,%5,%6,%7}, {%8,%9}, {%0,%1,%2,%3};"
        : "+f"(c[0]), "+f"(c[1]), "+f"(c[2]), "+f"(c[3])
        : "r"(a[0]), "r"(a[1]), "r"(a[2]), "r"(a[3]), "r"(b[0]), "r"(b[1]));
}

__device__ __forceinline__ float ex2f(float x) {
    float y; asm("ex2.approx.f32 %0, %1;" : "=f"(y) : "f"(x)); return y;
}

__device__ __forceinline__ uint32_t split_pair(float a, float b, uint32_t& lo) {
    __nv_bfloat162 h = __floats2bfloat162_rn(a, b);
    float ra = a - __bfloat162float(h.x);
    float rb = b - __bfloat162float(h.y);
    __nv_bfloat162 l = __floats2bfloat162_rn(ra, rb);
    lo = *reinterpret_cast<uint32_t*>(&l);
    return *reinterpret_cast<uint32_t*>(&h);
}

__device__ __forceinline__ size_t apermidx(int m, int kp) {
    const int mb = m >> 7, r = m & 127;
    const int kb = kp >> 4, kr = kp & 15;
    const int kt = kr >> 3, khalf = (kr >> 2) & 1, j = kr & 3;
    const int tile = kt * 8 + (r >> 4);
    const int lane = (r & 7) * 4 + j;
    const int areg = ((r >> 3) & 1) | (khalf << 1);
    return ((size_t)(mb * 32 + kb)) * 2048 + tile * 128 + lane * 4 + areg;
}
__device__ __forceinline__ size_t bpermidx(int n, int kp) {
    const int nb = n >> 7, r = n & 127;
    const int kb = kp >> 4, kr = kp & 15;
    const int kt = kr >> 3, khalf = (kr >> 2) & 1, j = kr & 3;
    const int ntile = r >> 3;
    const int lane = (r & 7) * 4 + j;
    return ((size_t)(nb * 32 + kb)) * 2048 +
           (kt * 8 + (ntile >> 1)) * 128 + lane * 4 + (ntile & 1) * 2 + khalf;
}
__device__ __forceinline__ size_t qfragidx(int bh, int t, int i) {
    const int ks = i >> 3, kk2 = i & 7;
    const int c2 = kk2 & 3, khalf = kk2 >> 2;
    const int row = t & 127, qb = t >> 7;
    const int wq = row >> 4, wrow = row & 15;
    const int areg = ((wrow >> 3) & 1) | (khalf << 1);
    return (size_t)bh * 65536 + qb * 4096 +
           ((wq * 4 + ks) * 32 + (wrow & 7) * 4 + c2) * 4 + areg;
}
__device__ __forceinline__ size_t kfragidx(int bh, int t, int i) {
    const int ks = i >> 3, kk2 = i & 7;
    const int c2 = kk2 & 3, khalf = kk2 >> 2;
    const int key = t & 63, ktile = t >> 6;
    const int ntile = key >> 3;
    const int lane = (key & 7) * 4 + c2;
    return (size_t)bh * 65536 + ktile * 2048 +
           (ks * 4 + (ntile >> 1)) * 128 + lane * 4 + (ntile & 1) * 2 + khalf;
}

// ---------------------------------------------------------------------------
// merged splits: grid.y = 0 -> x (A-perm), 1..4 -> weights (B-perm)
// ---------------------------------------------------------------------------
__global__ void split_all(const float2* __restrict__ sx,
                          const float2* __restrict__ s1, const float2* __restrict__ s2,
                          const float2* __restrict__ s3, const float2* __restrict__ s4,
                          uint32_t* __restrict__ xh, uint32_t* __restrict__ xl,
                          uint32_t* __restrict__ h1, uint32_t* __restrict__ l1,
                          uint32_t* __restrict__ h2, uint32_t* __restrict__ l2,
                          uint32_t* __restrict__ h3, uint32_t* __restrict__ l3,
                          uint32_t* __restrict__ h4, uint32_t* __restrict__ l4) {
    const int which = blockIdx.y;
    const int total = which == 0 ? M_ROWS * 512 : DD * 512;
    int i = blockIdx.x * blockDim.x + threadIdx.x;
    if (i >= total) return;
    const float2* src = which == 0 ? sx : which == 1 ? s1 : which == 2 ? s2
                      : which == 3 ? s3 : s4;
    uint32_t* dh = which == 0 ? xh : which == 1 ? h1 : which == 2 ? h2
                 : which == 3 ? h3 : h4;
    uint32_t* dl = which == 0 ? xl : which == 1 ? l1 : which == 2 ? l2
                 : which == 3 ? l3 : l4;
    float2 v = src[i];
    uint32_t lo, hi = split_pair(v.x, v.y, lo);
    const size_t idx = which == 0 ? apermidx(i >> 9, i & 511)
                                  : bpermidx(i >> 9, i & 511);
    dh[idx] = hi; dl[idx] = lo;
}

// ---------------------------------------------------------------------------
// Fused QKV GEMM (grid.x = 24: 8 n-blocks x {Q,K,V}). 256 threads, warp 64x32.
// ---------------------------------------------------------------------------
#define QSCALE 0.18033688011112042f   // 0.125 * log2(e)

__global__ __launch_bounds__(256, 2)
void gemm_qkv(const uint32_t* __restrict__ Ah, const uint32_t* __restrict__ Al,
              const uint32_t* __restrict__ Wqh, const uint32_t* __restrict__ Wql,
              const uint32_t* __restrict__ Wkh, const uint32_t* __restrict__ Wkl,
              const uint32_t* __restrict__ Wvh, const uint32_t* __restrict__ Wvl,
              const float2* __restrict__ fc2,
              uint32_t* __restrict__ qfh, uint32_t* __restrict__ qfl,
              uint32_t* __restrict__ kfh, uint32_t* __restrict__ kfl,
              uint32_t* __restrict__ vfh, uint32_t* __restrict__ vfl) {
    extern __shared__ __align__(16) uint32_t sm[];   // 64KB

    const int which = blockIdx.x >> 3;               // 0=Q 1=K 2=V
    const int nblk  = blockIdx.x & 7;
    const uint32_t* Wh = which == 0 ? Wqh : which == 1 ? Wkh : Wvh;
    const uint32_t* Wl = which == 0 ? Wql : which == 1 ? Wkl : Wvl;

    const int tid  = threadIdx.x;
    const int lane = tid & 31;
    const int w    = tid >> 5;
    const int wm   = w & 1;
    const int wn   = w >> 1;
    const int m0   = blockIdx.y * 128;
    const int n0   = nblk * 128;
    const size_t abase = ((size_t)blockIdx.y * 32) * 2048;
    const size_t bbase = ((size_t)nblk * 32) * 2048;
    const uint32_t smaddr = smem_u32(sm);

    float acc[4][4][4];
    #pragma unroll
    for (int i = 0; i < 4; i++)
        #pragma unroll
        for (int j = 0; j < 4; j++)
            #pragma unroll
            for (int r = 0; r < 4; r++) acc[i][j][r] = 0.f;

    auto issue = [&](int st, int kb) {
        const uint32_t dbase = smaddr + (uint32_t)st * 32768u + tid * 32u;
        const size_t ko = (size_t)kb * 2048 + tid * 8;
        CP16(dbase,          Ah + abase + ko);
        CP16(dbase + 16,     Ah + abase + ko + 4);
        CP16(dbase + 8192,   Al + abase + ko);
        CP16(dbase + 8208,   Al + abase + ko + 4);
        CP16(dbase + 16384,  Wh + bbase + ko);
        CP16(dbase + 16400,  Wh + bbase + ko + 4);
        CP16(dbase + 24576,  Wl + bbase + ko);
        CP16(dbase + 24592,  Wl + bbase + ko + 4);
        asm volatile("cp.async.commit_group;" ::: "memory");
    };

    issue(0, 0);

    for (int kb = 0; kb < 32; kb++) {
        asm volatile("cp.async.wait_group 0;" ::: "memory");
        __syncthreads();
        if (kb < 31) issue((kb + 1) & 1, kb + 1);

        const uint32_t* As = sm + (kb & 1) * 8192;
        const uint32_t* Bs = As + 4096;

        #pragma unroll
        for (int kt2 = 0; kt2 < 2; kt2++) {
            uint4 Afh[4], Afl[4];
            uint4 Bh4[2], Bl4[2];
            const uint32_t* pa_ = &As[(kt2 * 8 + wm * 4) * 128 + lane * 4];
            #pragma unroll
            for (int i = 0; i < 4; i++) {
                Afh[i] = *(const uint4*)(pa_ + i * 128);
                Afl[i] = *(const uint4*)(pa_ + 2048 + i * 128);
            }
            const uint32_t* pb_ = &Bs[(kt2 * 8 + wn * 2) * 128 + lane * 4];
            #pragma unroll
            for (int i = 0; i < 2; i++) {
                Bh4[i] = *(const uint4*)(pb_ + i * 128);
                Bl4[i] = *(const uint4*)(pb_ + 2048 + i * 128);
            }
            #pragma unroll
            for (int mt = 0; mt < 4; mt++)
                #pragma unroll
                for (int nt = 0; nt < 4; nt++) {
                    const uint32_t* bh = (const uint32_t*)&Bh4[nt >> 1] + (nt & 1) * 2;
                    const uint32_t* bl = (const uint32_t*)&Bl4[nt >> 1] + (nt & 1) * 2;
                    mma16816(acc[mt][nt], (const uint32_t*)&Afh[mt], bh);
                    mma16816(acc[mt][nt], (const uint32_t*)&Afh[mt], bl);
                    mma16816(acc[mt][nt], (const uint32_t*)&Afl[mt], bh);
                }
        }
    }

    // epilogue
    #pragma unroll
    for (int mt = 0; mt < 4; mt++) {
        #pragma unroll
        for (int nt = 0; nt < 4; nt++) {
            const int m = m0 + wm * 64 + mt * 16 + (lane >> 2);
            const int n = n0 + wn * 32 + nt * 8 + ((lane & 3) << 1);
            float* c = acc[mt][nt];
            const int b = m >> 11, t = m & 2047;
            const int h = n >> 6,  d = n & 63;
            const int bh = b * HH + h;
            if (which < 2) {
                const int i = d >> 1;
                #pragma unroll
                for (int rr = 0; rr < 2; rr++) {
                    const int tt = t + rr * 8;
                    const float2 cs = fc2[tt * 32 + i];
                    float o0 = c[rr*2] * cs.x - c[rr*2+1] * cs.y;
                    float o1 = c[rr*2] * cs.y + c[rr*2+1] * cs.x;
                    uint32_t lo, hi;
                    if (which == 0) {
                        hi = split_pair(o0 * QSCALE, o1 * QSCALE, lo);
                        const size_t qi = qfragidx(bh, tt, i);
                        qfh[qi] = hi; qfl[qi] = lo;
                    } else {
                        hi = split_pair(o0, o1, lo);
                        const size_t ki = kfragidx(bh, tt, i);
                        kfh[ki] = hi; kfl[ki] = lo;
                    }
                }
            } else {
                #pragma unroll
                for (int rr = 0; rr < 2; rr++) {
                    const int tt = t + rr * 8;
                    const int kt3 = tt >> 6, kpp = (tt & 63) >> 1, hf = tt & 1;
                    const int ks3 = kpp >> 3, kk3 = kpp & 7;
                    const int c3 = kk3 & 3, kh3 = kk3 >> 2;
                    #pragma unroll
                    for (int jj = 0; jj < 2; jj++) {
                        const int dd = d + jj;
                        const int ntile = dd >> 3;
                        const int vlane = (dd & 7) * 4 + c3;
                        const int slot = (ks3 * 4 + (ntile >> 1)) * 128 +
                                         vlane * 4 + (ntile & 1) * 2 + kh3;
                        const size_t u32i = (size_t)bh * 65536 + kt3 * 2048 + slot;
                        const float v = c[rr * 2 + jj];
                        __nv_bfloat16 hb = __float2bfloat16_rn(v);
                        __nv_bfloat16 lb = __float2bfloat16_rn(v - __bfloat162float(hb));
                        ((uint16_t*)vfh)[u32i * 2 + hf] = *(uint16_t*)&hb;
                        ((uint16_t*)vfl)[u32i * 2 + hf] = *(uint16_t*)&lb;
                    }
                }
            }
        }
    }
}

// ---------------------------------------------------------------------------
// FUSED attention + O-projection. Grid 768:
//   blocks 0..511  : attention (heavy-first), increments g_flags[b*16+qi] done.
//   blocks 512..767: gemm_o m-block (ordered qi-descending), spins on flags.
// Both paths: 256 threads, <=80KB dyn smem, 2 CTAs/SM.
// ---------------------------------------------------------------------------
__global__ __launch_bounds__(256, 2)
void attn_ogemm(const uint32_t* __restrict__ qfh, const uint32_t* __restrict__ qfl,
                const uint32_t* __restrict__ kfh, const uint32_t* __restrict__ kfl,
                const uint32_t* __restrict__ vfh, const uint32_t* __restrict__ vfl,
                uint32_t* __restrict__ aoh, uint32_t* __restrict__ aol,
                const uint32_t* __restrict__ Woh, const uint32_t* __restrict__ Wol,
                float* __restrict__ C) {
    extern __shared__ __align__(16) uint32_t sm[];
    const int tid = threadIdx.x;
    const int lane = tid & 31;
    const int w = tid >> 5;
    const uint32_t smaddr = smem_u32(sm);

    if (blockIdx.x < 512) {
        // ================= attention =================
        const int qi = 15 - ((int)blockIdx.x >> 5);
        const int bh = blockIdx.x & 31;
        const int b  = bh >> 4, hhd = bh & 15;
        const int q0 = qi * 128;
        const size_t hbase = (size_t)bh * 65536;
        uint32_t* qlo_s = sm + 16384;

        uint4 qfh_r[4];
        {
            const size_t qb = hbase + (size_t)qi * 4096;
            #pragma unroll
            for (int ks = 0; ks < 4; ks++) {
                const size_t o = qb + ((w * 4 + ks) * 32 + lane) * 4;
                qfh_r[ks] = *(const uint4*)&qfh[o];
            }
            #pragma unroll
            for (int i = 0; i < 4; i++) {
                const int id = i * 1024 + tid * 4;
                *(uint4*)&qlo_s[id] = *(const uint4*)&qfl[qb + id];
            }
        }
        __syncthreads();

        float oacc[8][4];
        #pragma unroll
        for (int dt = 0; dt < 8; dt++)
            #pragma unroll
            for (int r = 0; r < 4; r++) oacc[dt][r] = 0.f;
        float mr0 = -1e30f, mr1 = -1e30f, lr0 = 0.f, lr1 = 0.f;

        const int r0 = q0 + w * 16;
        const int ntiles = qi * 2 + 2;

        auto issue = [&](int st, int kt) {
            const uint32_t dbase = smaddr + (uint32_t)st * 32768u + tid * 32u;
            const size_t ko = hbase + (size_t)kt * 2048 + tid * 8;
            CP16(dbase,          kfh + ko);
            CP16(dbase + 16,     kfh + ko + 4);
            CP16(dbase + 8192,   kfl + ko);
            CP16(dbase + 8208,   kfl + ko + 4);
            CP16(dbase + 16384,  vfh + ko);
            CP16(dbase + 16400,  vfh + ko + 4);
            CP16(dbase + 24576,  vfl + ko);
            CP16(dbase + 24592,  vfl + ko + 4);
            asm volatile("cp.async.commit_group;" ::: "memory");
        };

        issue(0, 0);

        for (int kt = 0; kt < ntiles; kt++) {
            const int kt0 = kt * 64;
            asm volatile("cp.async.wait_group 0;" ::: "memory");
            __syncthreads();
            if (kt + 1 < ntiles) issue((kt + 1) & 1, kt + 1);

            const uint32_t* S = sm + (kt & 1) * 8192;

            if (kt0 <= r0 + 15) {
                float sacc[8][4];
                #pragma unroll
                for (int nt = 0; nt < 8; nt++)
                    #pragma unroll
                    for (int r = 0; r < 4; r++) sacc[nt][r] = 0.f;
                #pragma unroll
                for (int ks = 0; ks < 4; ks++) {
                    const uint4 qlo = *(const uint4*)&qlo_s[((w * 4 + ks) * 32 + lane) * 4];
                    #pragma unroll
                    for (int p = 0; p < 4; p++) {
                        const uint4 kh4 = *(const uint4*)&S[(ks * 4 + p) * 128 + lane * 4];
                        const uint4 kl4 = *(const uint4*)&S[2048 + (ks * 4 + p) * 128 + lane * 4];
                        #pragma unroll
                        for (int hh = 0; hh < 2; hh++) {
                            const int nt = p * 2 + hh;
                            const uint32_t* kbh = (const uint32_t*)&kh4 + hh * 2;
                            const uint32_t* kbl = (const uint32_t*)&kl4 + hh * 2;
                            mma16816(sacc[nt], (const uint32_t*)&qfh_r[ks], kbh);
                            mma16816(sacc[nt], (const uint32_t*)&qfh_r[ks], kbl);
                            mma16816(sacc[nt], (const uint32_t*)&qlo, kbh);
                        }
                    }
                }
                if (kt0 + 63 > r0) {
                    const int colb = kt0 + ((lane & 3) << 1);
                    const int rowb = r0 + (lane >> 2);
                    #pragma unroll
                    for (int nt = 0; nt < 8; nt++) {
                        #pragma unroll
                        for (int r = 0; r < 4; r++) {
                            const int col = colb + nt * 8 + (r & 1);
                            const int row = rowb + ((r >> 1) << 3);
                            if (col > row) sacc[nt][r] = -1e30f;
                        }
                    }
                }
                float mx0 = -1e30f, mx1 = -1e30f;
                #pragma unroll
                for (int nt = 0; nt < 8; nt++) {
                    mx0 = fmaxf(mx0, fmaxf(sacc[nt][0], sacc[nt][1]));
                    mx1 = fmaxf(mx1, fmaxf(sacc[nt][2], sacc[nt][3]));
                }
                mx0 = fmaxf(mx0, __shfl_xor_sync(0xffffffffu, mx0, 1));
                mx0 = fmaxf(mx0, __shfl_xor_sync(0xffffffffu, mx0, 2));
                mx1 = fmaxf(mx1, __shfl_xor_sync(0xffffffffu, mx1, 1));
                mx1 = fmaxf(mx1, __shfl_xor_sync(0xffffffffu, mx1, 2));
                const float mn0 = fmaxf(mr0, mx0);
                const float mn1 = fmaxf(mr1, mx1);
                const float corr0 = ex2f(mr0 - mn0);
                const float corr1 = ex2f(mr1 - mn1);
                mr0 = mn0; mr1 = mn1;
                float s0 = 0.f, s1 = 0.f;
                #pragma unroll
                for (int nt = 0; nt < 8; nt++) {
                    sacc[nt][0] = ex2f(sacc[nt][0] - mn0);
                    sacc[nt][1] = ex2f(sacc[nt][1] - mn0);
                    sacc[nt][2] = ex2f(sacc[nt][2] - mn1);
                    sacc[nt][3] = ex2f(sacc[nt][3] - mn1);
                    s0 += sacc[nt][0] + sacc[nt][1];
                    s1 += sacc[nt][2] + sacc[nt][3];
                }
                lr0 = lr0 * corr0 + s0;
                lr1 = lr1 * corr1 + s1;
                #pragma unroll
                for (int dt = 0; dt < 8; dt++) {
                    oacc[dt][0] *= corr0; oacc[dt][1] *= corr0;
                    oacc[dt][2] *= corr1; oacc[dt][3] *= corr1;
                }
                uint32_t pah[4][4], pal[4][4];
                #pragma unroll
                for (int ksp = 0; ksp < 4; ksp++) {
                    pah[ksp][0] = split_pair(sacc[2*ksp][0],   sacc[2*ksp][1],   pal[ksp][0]);
                    pah[ksp][1] = split_pair(sacc[2*ksp][2],   sacc[2*ksp][3],   pal[ksp][1]);
                    pah[ksp][2] = split_pair(sacc[2*ksp+1][0], sacc[2*ksp+1][1], pal[ksp][2]);
                    pah[ksp][3] = split_pair(sacc[2*ksp+1][2], sacc[2*ksp+1][3], pal[ksp][3]);
                }
                #pragma unroll
                for (int ksp = 0; ksp < 4; ksp++) {
                    #pragma unroll
                    for (int p = 0; p < 4; p++) {
                        const uint4 vh4 = *(const uint4*)&S[4096 + (ksp * 4 + p) * 128 + lane * 4];
                        const uint4 vl4 = *(const uint4*)&S[6144 + (ksp * 4 + p) * 128 + lane * 4];
                        #pragma unroll
                        for (int hh = 0; hh < 2; hh++) {
                            const int dt = p * 2 + hh;
                            const uint32_t* vbh = (const uint32_t*)&vh4 + hh * 2;
                            const uint32_t* vbl = (const uint32_t*)&vl4 + hh * 2;
                            mma16816(oacc[dt], pah[ksp], vbh);
                            mma16816(oacc[dt], pal[ksp], vbh);
                            mma16816(oacc[dt], pah[ksp], vbl);
                        }
                    }
                }
            }
        }

        lr0 += __shfl_xor_sync(0xffffffffu, lr0, 1);
        lr0 += __shfl_xor_sync(0xffffffffu, lr0, 2);
        lr1 += __shfl_xor_sync(0xffffffffu, lr1, 1);
        lr1 += __shfl_xor_sync(0xffffffffu, lr1, 2);
        const float inv0 = 1.f / lr0;
        const float inv1 = 1.f / lr1;
        const int t0 = r0 + (lane >> 2);
        const int t1 = t0 + 8;
        #pragma unroll
        for (int dt = 0; dt < 8; dt++) {
            const int kp = hhd * 32 + dt * 4 + (lane & 3);
            uint32_t lo;
            uint32_t hi = split_pair(oacc[dt][0] * inv0, oacc[dt][1] * inv0, lo);
            const size_t i0 = apermidx(b * TT + t0, kp);
            aoh[i0] = hi; aol[i0] = lo;
            hi = split_pair(oacc[dt][2] * inv1, oacc[dt][3] * inv1, lo);
            const size_t i1 = apermidx(b * TT + t1, kp);
            aoh[i1] = hi; aol[i1] = lo;
        }

        // signal completion of (b, qi) for this head
        __threadfence();
        __syncthreads();
        if (tid == 0) atomicAdd(&g_flags[b * 16 + qi], 1);
    } else {
        // ================= O-projection m-block =================
        const int ob = blockIdx.x - 512;
        const int j  = ob >> 3;                 // 0..31, qi-descending order
        const int qi_o = 15 - (j >> 1);
        const int bo   = j & 1;
        const int mb   = bo * 16 + qi_o;
        const int nblk = ob & 7;

        if (tid == 0) {
            while (*(volatile int*)&g_flags[mb] < 16) __nanosleep(200);
        }
        __syncthreads();
        __threadfence();

        const int m0 = mb * 128;
        const int n0 = nblk * 128;
        const size_t abase = ((size_t)mb * 32) * 2048;
        const size_t bbase = ((size_t)nblk * 32) * 2048;
        const int wm = w & 1;
        const int wn = w >> 1;

        float acc[4][4][4];
        #pragma unroll
        for (int i = 0; i < 4; i++)
            #pragma unroll
            for (int jj = 0; jj < 4; jj++)
                #pragma unroll
                for (int r = 0; r < 4; r++) acc[i][jj][r] = 0.f;

        auto issue = [&](int st, int kb) {
            const uint32_t dbase = smaddr + (uint32_t)st * 32768u + tid * 32u;
            const size_t ko = (size_t)kb * 2048 + tid * 8;
            CP16(dbase,          aoh + abase + ko);
            CP16(dbase + 16,     aoh + abase + ko + 4);
            CP16(dbase + 8192,   aol + abase + ko);
            CP16(dbase + 8208,   aol + abase + ko + 4);
            CP16(dbase + 16384,  Woh + bbase + ko);
            CP16(dbase + 16400,  Woh + bbase + ko + 4);
            CP16(dbase + 24576,  Wol + bbase + ko);
            CP16(dbase + 24592,  Wol + bbase + ko + 4);
            asm volatile("cp.async.commit_group;" ::: "memory");
        };

        issue(0, 0);

        for (int kb = 0; kb < 32; kb++) {
            asm volatile("cp.async.wait_group 0;" ::: "memory");
            __syncthreads();
            if (kb < 31) issue((kb + 1) & 1, kb + 1);

            const uint32_t* As = sm + (kb & 1) * 8192;
            const uint32_t* Bs = As + 4096;

            #pragma unroll
            for (int kt2 = 0; kt2 < 2; kt2++) {
                uint4 Afh[4], Afl[4];
                uint4 Bh4[2], Bl4[2];
                const uint32_t* pa_ = &As[(kt2 * 8 + wm * 4) * 128 + lane * 4];
                #pragma unroll
                for (int i = 0; i < 4; i++) {
                    Afh[i] = *(const uint4*)(pa_ + i * 128);
                    Afl[i] = *(const uint4*)(pa_ + 2048 + i * 128);
                }
                const uint32_t* pb_ = &Bs[(kt2 * 8 + wn * 2) * 128 + lane * 4];
                #pragma unroll
                for (int i = 0; i < 2; i++) {
                    Bh4[i] = *(const uint4*)(pb_ + i * 128);
                    Bl4[i] = *(const uint4*)(pb_ + 2048 + i * 128);
                }
                #pragma unroll
                for (int mt = 0; mt < 4; mt++)
                    #pragma unroll
                    for (int nt = 0; nt < 4; nt++) {
                        const uint32_t* bh = (const uint32_t*)&Bh4[nt >> 1] + (nt & 1) * 2;
                        const uint32_t* bl = (const uint32_t*)&Bl4[nt >> 1] + (nt & 1) * 2;
                        mma16816(acc[mt][nt], (const uint32_t*)&Afh[mt], bh);
                        mma16816(acc[mt][nt], (const uint32_t*)&Afh[mt], bl);
                        mma16816(acc[mt][nt], (const uint32_t*)&Afl[mt], bh);
                    }
            }
        }

        #pragma unroll
        for (int mt = 0; mt < 4; mt++) {
            #pragma unroll
            for (int nt = 0; nt < 4; nt++) {
                const int m = m0 + wm * 64 + mt * 16 + (lane >> 2);
                const int n = n0 + wn * 32 + nt * 8 + ((lane & 3) << 1);
                const float* c = acc[mt][nt];
                *(float2*)&C[(size_t)m * 1024 + n]       = make_float2(c[0], c[1]);
                *(float2*)&C[(size_t)(m + 8) * 1024 + n] = make_float2(c[2], c[3]);
            }
        }
    }
}

// ---------------------------------------------------------------------------
extern "C" void kernel_launch(void* const* d_in, const int* in_sizes, int n_in,
                              void* d_out, int out_size) {
    const float* x  = (const float*)d_in[0];
    const float* wq = (const float*)d_in[1];
    const float* wk = (const float*)d_in[2];
    const float* wv = (const float*)d_in[3];
    const float* wo = (const float*)d_in[4];
    const float* fc = (const float*)d_in[5];
    float* out = (float*)d_out;

    uint32_t *qfhp, *qflp, *kfhp, *kflp, *vfhp, *vflp;
    uint32_t *xhp, *xlp, *aohp, *aolp;
    uint32_t *wqhp, *wqlp, *wkhp, *wklp, *wvhp, *wvlp, *wohp, *wolp;
    int* flagsp;
    cudaGetSymbolAddress((void**)&qfhp, g_qfh);
    cudaGetSymbolAddress((void**)&qflp, g_qfl);
    cudaGetSymbolAddress((void**)&kfhp, g_kfh);
    cudaGetSymbolAddress((void**)&kflp, g_kfl);
    cudaGetSymbolAddress((void**)&vfhp, g_vfh);
    cudaGetSymbolAddress((void**)&vflp, g_vfl);
    cudaGetSymbolAddress((void**)&xhp, g_xh);
    cudaGetSymbolAddress((void**)&xlp, g_xl);
    cudaGetSymbolAddress((void**)&aohp, g_aoh);
    cudaGetSymbolAddress((void**)&aolp, g_aol);
    cudaGetSymbolAddress((void**)&wqhp, g_wqh);
    cudaGetSymbolAddress((void**)&wqlp, g_wql);
    cudaGetSymbolAddress((void**)&wkhp, g_wkh);
    cudaGetSymbolAddress((void**)&wklp, g_wkl);
    cudaGetSymbolAddress((void**)&wvhp, g_wvh);
    cudaGetSymbolAddress((void**)&wvlp, g_wvl);
    cudaGetSymbolAddress((void**)&wohp, g_woh);
    cudaGetSymbolAddress((void**)&wolp, g_wol);
    cudaGetSymbolAddress((void**)&flagsp, g_flags);

    const int DYNSZ  = 65536;
    const int ADYNSZ = 81920;
    cudaFuncSetAttribute(gemm_qkv,  cudaFuncAttributeMaxDynamicSharedMemorySize, DYNSZ);
    cudaFuncSetAttribute(attn_ogemm, cudaFuncAttributeMaxDynamicSharedMemorySize, ADYNSZ);

    cudaMemsetAsync(flagsp, 0, 32 * sizeof(int));

    const int xpairs = M_ROWS * 512;   // = 2,097,152 (max of x / weight pair counts)
    dim3 sgrid((xpairs + 255) / 256, 5);
    split_all<<<sgrid, 256>>>((const float2*)x, (const float2*)wq, (const float2*)wk,
                              (const float2*)wv, (const float2*)wo,
                              xhp, xlp, wqhp, wqlp, wkhp, wklp, wvhp, wvlp,
                              wohp, wolp);

    dim3 qkvgrid(24, M_ROWS / 128);   // (24, 32)
    gemm_qkv<<<qkvgrid, 256, DYNSZ>>>(xhp, xlp, wqhp, wqlp, wkhp, wklp, wvhp, wvlp,
                                      (const float2*)fc, qfhp, qflp, kfhp, kflp,
                                      vfhp, vflp);

    attn_ogemm<<<768, 256, ADYNSZ>>>(qfhp, qflp, kfhp, kflp, vfhp, vflp,
                                     aohp, aolp, wohp, wolp, out);
}

// round 15
// speedup vs baseline: 1.0211x; 1.0211x over previous
#include <cuda_runtime.h>
#include <cuda_bf16.h>
#include <cstdint>

#define BB 2
#define TT 2048
#define DD 1024
#define HH 16
#define HD 64
#define M_ROWS (BB*TT)   // 4096

// ---------------------------------------------------------------------------
// Device scratch (allocation-free). Fragment-image layouts; B-side PAIRED.
// ---------------------------------------------------------------------------
__device__ uint32_t g_qfh[BB*HH*16*4096];
__device__ uint32_t g_qfl[BB*HH*16*4096];
__device__ uint32_t g_kfh[BB*HH*32*2048];
__device__ uint32_t g_kfl[BB*HH*32*2048];
__device__ uint32_t g_vfh[BB*HH*32*2048];
__device__ uint32_t g_vfl[BB*HH*32*2048];
__device__ uint32_t g_xh[M_ROWS*512];
__device__ uint32_t g_xl[M_ROWS*512];
__device__ uint32_t g_wqh[DD*512], g_wql[DD*512];
__device__ uint32_t g_wkh[DD*512], g_wkl[DD*512];
__device__ uint32_t g_wvh[DD*512], g_wvl[DD*512];
__device__ uint32_t g_woh[DD*512], g_wol[DD*512];
__device__ uint32_t g_aoh[M_ROWS*512];
__device__ uint32_t g_aol[M_ROWS*512];
__device__ int g_flags[32];   // per (b*16 + qi) attention-completion counters

// ---------------------------------------------------------------------------
// helpers
// ---------------------------------------------------------------------------
__device__ __forceinline__ uint32_t smem_u32(const void* p) {
    return (uint32_t)__cvta_generic_to_shared(p);
}

#define CP16(d, s) asm volatile("cp.async.cg.shared.global [%0], [%1], 16;" \
                                :: "r"(d), "l"(s) : "memory")

__device__ __forceinline__ void mma16816(float* c, const uint32_t* a, const uint32_t* b) {
    asm volatile(
        "mma.sync.aligned.m16n8k16.row.col.f32.bf16.bf16.f32 "
        "{%0,%1,%2,%3}, {%4,%5,%6,%7}, {%8,%9}, {%0,%1,%2,%3};"
        : "+f"(c[0]), "+f"(c[1]), "+f"(c[2]), "+f"(c[3])
        : "r"(a[0]), "r"(a[1]), "r"(a[2]), "r"(a[3]), "r"(b[0]), "r"(b[1]));
}

__device__ __forceinline__ float ex2f(float x) {
    float y; asm("ex2.approx.f32 %0, %1;" : "=f"(y) : "f"(x)); return y;
}

__device__ __forceinline__ uint32_t split_pair(float a, float b, uint32_t& lo) {
    __nv_bfloat162 h = __floats2bfloat162_rn(a, b);
    float ra = a - __bfloat162float(h.x);
    float rb = b - __bfloat162float(h.y);
    __nv_bfloat162 l = __floats2bfloat162_rn(ra, rb);
    lo = *reinterpret_cast<uint32_t*>(&l);
    return *reinterpret_cast<uint32_t*>(&h);
}

__device__ __forceinline__ size_t apermidx(int m, int kp) {
    const int mb = m >> 7, r = m & 127;
    const int kb = kp >> 4, kr = kp & 15;
    const int kt = kr >> 3, khalf = (kr >> 2) & 1, j = kr & 3;
    const int tile = kt * 8 + (r >> 4);
    const int lane = (r & 7) * 4 + j;
    const int areg = ((r >> 3) & 1) | (khalf << 1);
    return ((size_t)(mb * 32 + kb)) * 2048 + tile * 128 + lane * 4 + areg;
}
__device__ __forceinline__ size_t bpermidx(int n, int kp) {
    const int nb = n >> 7, r = n & 127;
    const int kb = kp >> 4, kr = kp & 15;
    const int kt = kr >> 3, khalf = (kr >> 2) & 1, j = kr & 3;
    const int ntile = r >> 3;
    const int lane = (r & 7) * 4 + j;
    return ((size_t)(nb * 32 + kb)) * 2048 +
           (kt * 8 + (ntile >> 1)) * 128 + lane * 4 + (ntile & 1) * 2 + khalf;
}
__device__ __forceinline__ size_t qfragidx(int bh, int t, int i) {
    const int ks = i >> 3, kk2 = i & 7;
    const int c2 = kk2 & 3, khalf = kk2 >> 2;
    const int row = t & 127, qb = t >> 7;
    const int wq = row >> 4, wrow = row & 15;
    const int areg = ((wrow >> 3) & 1) | (khalf << 1);
    return (size_t)bh * 65536 + qb * 4096 +
           ((wq * 4 + ks) * 32 + (wrow & 7) * 4 + c2) * 4 + areg;
}
__device__ __forceinline__ size_t kfragidx(int bh, int t, int i) {
    const int ks = i >> 3, kk2 = i & 7;
    const int c2 = kk2 & 3, khalf = kk2 >> 2;
    const int key = t & 63, ktile = t >> 6;
    const int ntile = key >> 3;
    const int lane = (key & 7) * 4 + c2;
    return (size_t)bh * 65536 + ktile * 2048 +
           (ks * 4 + (ntile >> 1)) * 128 + lane * 4 + (ntile & 1) * 2 + khalf;
}

// ---------------------------------------------------------------------------
// splits (two right-sized launches, as in R13)
// ---------------------------------------------------------------------------
__global__ void split_permA(const float2* __restrict__ src,
                            uint32_t* __restrict__ dh, uint32_t* __restrict__ dl,
                            int total) {
    int i = blockIdx.x * blockDim.x + threadIdx.x;
    if (i >= total) return;
    float2 v = src[i];
    uint32_t lo, hi = split_pair(v.x, v.y, lo);
    const size_t idx = apermidx(i >> 9, i & 511);
    dh[idx] = hi; dl[idx] = lo;
}
__global__ void split_permB4(const float2* __restrict__ s0, const float2* __restrict__ s1,
                             const float2* __restrict__ s2, const float2* __restrict__ s3,
                             uint32_t* __restrict__ h0, uint32_t* __restrict__ l0,
                             uint32_t* __restrict__ h1, uint32_t* __restrict__ l1,
                             uint32_t* __restrict__ h2, uint32_t* __restrict__ l2,
                             uint32_t* __restrict__ h3, uint32_t* __restrict__ l3,
                             int total) {
    int i = blockIdx.x * blockDim.x + threadIdx.x;
    if (i >= total) return;
    const int which = blockIdx.y;
    const float2* src = which == 0 ? s0 : which == 1 ? s1 : which == 2 ? s2 : s3;
    uint32_t* dh = which == 0 ? h0 : which == 1 ? h1 : which == 2 ? h2 : h3;
    uint32_t* dl = which == 0 ? l0 : which == 1 ? l1 : which == 2 ? l2 : l3;
    float2 v = src[i];
    uint32_t lo, hi = split_pair(v.x, v.y, lo);
    const size_t idx = bpermidx(i >> 9, i & 511);
    dh[idx] = hi; dl[idx] = lo;
}

// ---------------------------------------------------------------------------
// Fused QKV GEMM (grid.x = 24: 8 n-blocks x {Q,K,V}). 256 threads, warp 64x32.
// ---------------------------------------------------------------------------
#define QSCALE 0.18033688011112042f   // 0.125 * log2(e)

__global__ __launch_bounds__(256, 2)
void gemm_qkv(const uint32_t* __restrict__ Ah, const uint32_t* __restrict__ Al,
              const uint32_t* __restrict__ Wqh, const uint32_t* __restrict__ Wql,
              const uint32_t* __restrict__ Wkh, const uint32_t* __restrict__ Wkl,
              const uint32_t* __restrict__ Wvh, const uint32_t* __restrict__ Wvl,
              const float2* __restrict__ fc2,
              uint32_t* __restrict__ qfh, uint32_t* __restrict__ qfl,
              uint32_t* __restrict__ kfh, uint32_t* __restrict__ kfl,
              uint32_t* __restrict__ vfh, uint32_t* __restrict__ vfl) {
    extern __shared__ __align__(16) uint32_t sm[];   // 64KB

    const int which = blockIdx.x >> 3;               // 0=Q 1=K 2=V
    const int nblk  = blockIdx.x & 7;
    const uint32_t* Wh = which == 0 ? Wqh : which == 1 ? Wkh : Wvh;
    const uint32_t* Wl = which == 0 ? Wql : which == 1 ? Wkl : Wvl;

    const int tid  = threadIdx.x;
    const int lane = tid & 31;
    const int w    = tid >> 5;
    const int wm   = w & 1;
    const int wn   = w >> 1;
    const int m0   = blockIdx.y * 128;
    const int n0   = nblk * 128;
    const size_t abase = ((size_t)blockIdx.y * 32) * 2048;
    const size_t bbase = ((size_t)nblk * 32) * 2048;
    const uint32_t smaddr = smem_u32(sm);

    float acc[4][4][4];
    #pragma unroll
    for (int i = 0; i < 4; i++)
        #pragma unroll
        for (int j = 0; j < 4; j++)
            #pragma unroll
            for (int r = 0; r < 4; r++) acc[i][j][r] = 0.f;

    auto issue = [&](int st, int kb) {
        const uint32_t dbase = smaddr + (uint32_t)st * 32768u + tid * 32u;
        const size_t ko = (size_t)kb * 2048 + tid * 8;
        CP16(dbase,          Ah + abase + ko);
        CP16(dbase + 16,     Ah + abase + ko + 4);
        CP16(dbase + 8192,   Al + abase + ko);
        CP16(dbase + 8208,   Al + abase + ko + 4);
        CP16(dbase + 16384,  Wh + bbase + ko);
        CP16(dbase + 16400,  Wh + bbase + ko + 4);
        CP16(dbase + 24576,  Wl + bbase + ko);
        CP16(dbase + 24592,  Wl + bbase + ko + 4);
        asm volatile("cp.async.commit_group;" ::: "memory");
    };

    issue(0, 0);

    for (int kb = 0; kb < 32; kb++) {
        asm volatile("cp.async.wait_group 0;" ::: "memory");
        __syncthreads();
        if (kb < 31) issue((kb + 1) & 1, kb + 1);

        const uint32_t* As = sm + (kb & 1) * 8192;
        const uint32_t* Bs = As + 4096;

        #pragma unroll
        for (int kt2 = 0; kt2 < 2; kt2++) {
            uint4 Afh[4], Afl[4];
            uint4 Bh4[2], Bl4[2];
            const uint32_t* pa_ = &As[(kt2 * 8 + wm * 4) * 128 + lane * 4];
            #pragma unroll
            for (int i = 0; i < 4; i++) {
                Afh[i] = *(const uint4*)(pa_ + i * 128);
                Afl[i] = *(const uint4*)(pa_ + 2048 + i * 128);
            }
            const uint32_t* pb_ = &Bs[(kt2 * 8 + wn * 2) * 128 + lane * 4];
            #pragma unroll
            for (int i = 0; i < 2; i++) {
                Bh4[i] = *(const uint4*)(pb_ + i * 128);
                Bl4[i] = *(const uint4*)(pb_ + 2048 + i * 128);
            }
            #pragma unroll
            for (int mt = 0; mt < 4; mt++)
                #pragma unroll
                for (int nt = 0; nt < 4; nt++) {
                    const uint32_t* bh = (const uint32_t*)&Bh4[nt >> 1] + (nt & 1) * 2;
                    const uint32_t* bl = (const uint32_t*)&Bl4[nt >> 1] + (nt & 1) * 2;
                    mma16816(acc[mt][nt], (const uint32_t*)&Afh[mt], bh);
                    mma16816(acc[mt][nt], (const uint32_t*)&Afh[mt], bl);
                    mma16816(acc[mt][nt], (const uint32_t*)&Afl[mt], bh);
                }
        }
    }

    // epilogue
    #pragma unroll
    for (int mt = 0; mt < 4; mt++) {
        #pragma unroll
        for (int nt = 0; nt < 4; nt++) {
            const int m = m0 + wm * 64 + mt * 16 + (lane >> 2);
            const int n = n0 + wn * 32 + nt * 8 + ((lane & 3) << 1);
            float* c = acc[mt][nt];
            const int b = m >> 11, t = m & 2047;
            const int h = n >> 6,  d = n & 63;
            const int bh = b * HH + h;
            if (which < 2) {
                const int i = d >> 1;
                #pragma unroll
                for (int rr = 0; rr < 2; rr++) {
                    const int tt = t + rr * 8;
                    const float2 cs = fc2[tt * 32 + i];
                    float o0 = c[rr*2] * cs.x - c[rr*2+1] * cs.y;
                    float o1 = c[rr*2] * cs.y + c[rr*2+1] * cs.x;
                    uint32_t lo, hi;
                    if (which == 0) {
                        hi = split_pair(o0 * QSCALE, o1 * QSCALE, lo);
                        const size_t qi = qfragidx(bh, tt, i);
                        qfh[qi] = hi; qfl[qi] = lo;
                    } else {
                        hi = split_pair(o0, o1, lo);
                        const size_t ki = kfragidx(bh, tt, i);
                        kfh[ki] = hi; kfl[ki] = lo;
                    }
                }
            } else {
                #pragma unroll
                for (int rr = 0; rr < 2; rr++) {
                    const int tt = t + rr * 8;
                    const int kt3 = tt >> 6, kpp = (tt & 63) >> 1, hf = tt & 1;
                    const int ks3 = kpp >> 3, kk3 = kpp & 7;
                    const int c3 = kk3 & 3, kh3 = kk3 >> 2;
                    #pragma unroll
                    for (int jj = 0; jj < 2; jj++) {
                        const int dd = d + jj;
                        const int ntile = dd >> 3;
                        const int vlane = (dd & 7) * 4 + c3;
                        const int slot = (ks3 * 4 + (ntile >> 1)) * 128 +
                                         vlane * 4 + (ntile & 1) * 2 + kh3;
                        const size_t u32i = (size_t)bh * 65536 + kt3 * 2048 + slot;
                        const float v = c[rr * 2 + jj];
                        __nv_bfloat16 hb = __float2bfloat16_rn(v);
                        __nv_bfloat16 lb = __float2bfloat16_rn(v - __bfloat162float(hb));
                        ((uint16_t*)vfh)[u32i * 2 + hf] = *(uint16_t*)&hb;
                        ((uint16_t*)vfl)[u32i * 2 + hf] = *(uint16_t*)&lb;
                    }
                }
            }
        }
    }
}

// ---------------------------------------------------------------------------
// FUSED attention + O-projection. Grid 768:
//   blocks 0..511  : attention (heavy-first), increments g_flags[b*16+qi].
//   blocks 512..767: gemm_o m-block (qi-descending), spins on flags.
// ---------------------------------------------------------------------------
__global__ __launch_bounds__(256, 2)
void attn_ogemm(const uint32_t* __restrict__ qfh, const uint32_t* __restrict__ qfl,
                const uint32_t* __restrict__ kfh, const uint32_t* __restrict__ kfl,
                const uint32_t* __restrict__ vfh, const uint32_t* __restrict__ vfl,
                uint32_t* __restrict__ aoh, uint32_t* __restrict__ aol,
                const uint32_t* __restrict__ Woh, const uint32_t* __restrict__ Wol,
                float* __restrict__ C) {
    extern __shared__ __align__(16) uint32_t sm[];
    const int tid = threadIdx.x;
    const int lane = tid & 31;
    const int w = tid >> 5;
    const uint32_t smaddr = smem_u32(sm);

    if (blockIdx.x < 512) {
        // ================= attention =================
        const int qi = 15 - ((int)blockIdx.x >> 5);
        const int bh = blockIdx.x & 31;
        const int b  = bh >> 4, hhd = bh & 15;
        const int q0 = qi * 128;
        const size_t hbase = (size_t)bh * 65536;
        uint32_t* qlo_s = sm + 16384;

        uint4 qfh_r[4];
        {
            const size_t qb = hbase + (size_t)qi * 4096;
            #pragma unroll
            for (int ks = 0; ks < 4; ks++) {
                const size_t o = qb + ((w * 4 + ks) * 32 + lane) * 4;
                qfh_r[ks] = *(const uint4*)&qfh[o];
            }
            #pragma unroll
            for (int i = 0; i < 4; i++) {
                const int id = i * 1024 + tid * 4;
                *(uint4*)&qlo_s[id] = *(const uint4*)&qfl[qb + id];
            }
        }
        __syncthreads();

        float oacc[8][4];
        #pragma unroll
        for (int dt = 0; dt < 8; dt++)
            #pragma unroll
            for (int r = 0; r < 4; r++) oacc[dt][r] = 0.f;
        float mr0 = -1e30f, mr1 = -1e30f, lr0 = 0.f, lr1 = 0.f;

        const int r0 = q0 + w * 16;
        const int ntiles = qi * 2 + 2;

        auto issue = [&](int st, int kt) {
            const uint32_t dbase = smaddr + (uint32_t)st * 32768u + tid * 32u;
            const size_t ko = hbase + (size_t)kt * 2048 + tid * 8;
            CP16(dbase,          kfh + ko);
            CP16(dbase + 16,     kfh + ko + 4);
            CP16(dbase + 8192,   kfl + ko);
            CP16(dbase + 8208,   kfl + ko + 4);
            CP16(dbase + 16384,  vfh + ko);
            CP16(dbase + 16400,  vfh + ko + 4);
            CP16(dbase + 24576,  vfl + ko);
            CP16(dbase + 24592,  vfl + ko + 4);
            asm volatile("cp.async.commit_group;" ::: "memory");
        };

        issue(0, 0);

        for (int kt = 0; kt < ntiles; kt++) {
            const int kt0 = kt * 64;
            asm volatile("cp.async.wait_group 0;" ::: "memory");
            __syncthreads();
            if (kt + 1 < ntiles) issue((kt + 1) & 1, kt + 1);

            const uint32_t* S = sm + (kt & 1) * 8192;

            if (kt0 <= r0 + 15) {
                float sacc[8][4];
                #pragma unroll
                for (int nt = 0; nt < 8; nt++)
                    #pragma unroll
                    for (int r = 0; r < 4; r++) sacc[nt][r] = 0.f;
                #pragma unroll
                for (int ks = 0; ks < 4; ks++) {
                    const uint4 qlo = *(const uint4*)&qlo_s[((w * 4 + ks) * 32 + lane) * 4];
                    #pragma unroll
                    for (int p = 0; p < 4; p++) {
                        const uint4 kh4 = *(const uint4*)&S[(ks * 4 + p) * 128 + lane * 4];
                        const uint4 kl4 = *(const uint4*)&S[2048 + (ks * 4 + p) * 128 + lane * 4];
                        #pragma unroll
                        for (int hh = 0; hh < 2; hh++) {
                            const int nt = p * 2 + hh;
                            const uint32_t* kbh = (const uint32_t*)&kh4 + hh * 2;
                            const uint32_t* kbl = (const uint32_t*)&kl4 + hh * 2;
                            mma16816(sacc[nt], (const uint32_t*)&qfh_r[ks], kbh);
                            mma16816(sacc[nt], (const uint32_t*)&qfh_r[ks], kbl);
                            mma16816(sacc[nt], (const uint32_t*)&qlo, kbh);
                        }
                    }
                }
                if (kt0 + 63 > r0) {
                    const int colb = kt0 + ((lane & 3) << 1);
                    const int rowb = r0 + (lane >> 2);
                    #pragma unroll
                    for (int nt = 0; nt < 8; nt++) {
                        #pragma unroll
                        for (int r = 0; r < 4; r++) {
                            const int col = colb + nt * 8 + (r & 1);
                            const int row = rowb + ((r >> 1) << 3);
                            if (col > row) sacc[nt][r] = -1e30f;
                        }
                    }
                }
                float mx0 = -1e30f, mx1 = -1e30f;
                #pragma unroll
                for (int nt = 0; nt < 8; nt++) {
                    mx0 = fmaxf(mx0, fmaxf(sacc[nt][0], sacc[nt][1]));
                    mx1 = fmaxf(mx1, fmaxf(sacc[nt][2], sacc[nt][3]));
                }
                mx0 = fmaxf(mx0, __shfl_xor_sync(0xffffffffu, mx0, 1));
                mx0 = fmaxf(mx0, __shfl_xor_sync(0xffffffffu, mx0, 2));
                mx1 = fmaxf(mx1, __shfl_xor_sync(0xffffffffu, mx1, 1));
                mx1 = fmaxf(mx1, __shfl_xor_sync(0xffffffffu, mx1, 2));
                const float mn0 = fmaxf(mr0, mx0);
                const float mn1 = fmaxf(mr1, mx1);
                const float corr0 = ex2f(mr0 - mn0);
                const float corr1 = ex2f(mr1 - mn1);
                mr0 = mn0; mr1 = mn1;
                float s0 = 0.f, s1 = 0.f;
                #pragma unroll
                for (int nt = 0; nt < 8; nt++) {
                    sacc[nt][0] = ex2f(sacc[nt][0] - mn0);
                    sacc[nt][1] = ex2f(sacc[nt][1] - mn0);
                    sacc[nt][2] = ex2f(sacc[nt][2] - mn1);
                    sacc[nt][3] = ex2f(sacc[nt][3] - mn1);
                    s0 += sacc[nt][0] + sacc[nt][1];
                    s1 += sacc[nt][2] + sacc[nt][3];
                }
                lr0 = lr0 * corr0 + s0;
                lr1 = lr1 * corr1 + s1;
                #pragma unroll
                for (int dt = 0; dt < 8; dt++) {
                    oacc[dt][0] *= corr0; oacc[dt][1] *= corr0;
                    oacc[dt][2] *= corr1; oacc[dt][3] *= corr1;
                }
                uint32_t pah[4][4], pal[4][4];
                #pragma unroll
                for (int ksp = 0; ksp < 4; ksp++) {
                    pah[ksp][0] = split_pair(sacc[2*ksp][0],   sacc[2*ksp][1],   pal[ksp][0]);
                    pah[ksp][1] = split_pair(sacc[2*ksp][2],   sacc[2*ksp][3],   pal[ksp][1]);
                    pah[ksp][2] = split_pair(sacc[2*ksp+1][0], sacc[2*ksp+1][1], pal[ksp][2]);
                    pah[ksp][3] = split_pair(sacc[2*ksp+1][2], sacc[2*ksp+1][3], pal[ksp][3]);
                }
                #pragma unroll
                for (int ksp = 0; ksp < 4; ksp++) {
                    #pragma unroll
                    for (int p = 0; p < 4; p++) {
                        const uint4 vh4 = *(const uint4*)&S[4096 + (ksp * 4 + p) * 128 + lane * 4];
                        const uint4 vl4 = *(const uint4*)&S[6144 + (ksp * 4 + p) * 128 + lane * 4];
                        #pragma unroll
                        for (int hh = 0; hh < 2; hh++) {
                            const int dt = p * 2 + hh;
                            const uint32_t* vbh = (const uint32_t*)&vh4 + hh * 2;
                            const uint32_t* vbl = (const uint32_t*)&vl4 + hh * 2;
                            mma16816(oacc[dt], pah[ksp], vbh);
                            mma16816(oacc[dt], pal[ksp], vbh);
                            mma16816(oacc[dt], pah[ksp], vbl);
                        }
                    }
                }
            }
        }

        lr0 += __shfl_xor_sync(0xffffffffu, lr0, 1);
        lr0 += __shfl_xor_sync(0xffffffffu, lr0, 2);
        lr1 += __shfl_xor_sync(0xffffffffu, lr1, 1);
        lr1 += __shfl_xor_sync(0xffffffffu, lr1, 2);
        const float inv0 = 1.f / lr0;
        const float inv1 = 1.f / lr1;
        const int t0 = r0 + (lane >> 2);
        const int t1 = t0 + 8;
        #pragma unroll
        for (int dt = 0; dt < 8; dt++) {
            const int kp = hhd * 32 + dt * 4 + (lane & 3);
            uint32_t lo;
            uint32_t hi = split_pair(oacc[dt][0] * inv0, oacc[dt][1] * inv0, lo);
            const size_t i0 = apermidx(b * TT + t0, kp);
            aoh[i0] = hi; aol[i0] = lo;
            hi = split_pair(oacc[dt][2] * inv1, oacc[dt][3] * inv1, lo);
            const size_t i1 = apermidx(b * TT + t1, kp);
            aoh[i1] = hi; aol[i1] = lo;
        }

        __threadfence();
        __syncthreads();
        if (tid == 0) atomicAdd(&g_flags[b * 16 + qi], 1);
    } else {
        // ================= O-projection m-block =================
        const int ob = blockIdx.x - 512;
        const int j  = ob >> 3;
        const int qi_o = 15 - (j >> 1);
        const int bo   = j & 1;
        const int mb   = bo * 16 + qi_o;
        const int nblk = ob & 7;

        if (tid == 0) {
            while (*(volatile int*)&g_flags[mb] < 16) __nanosleep(200);
        }
        __syncthreads();
        __threadfence();

        const int m0 = mb * 128;
        const int n0 = nblk * 128;
        const size_t abase = ((size_t)mb * 32) * 2048;
        const size_t bbase = ((size_t)nblk * 32) * 2048;
        const int wm = w & 1;
        const int wn = w >> 1;

        float acc[4][4][4];
        #pragma unroll
        for (int i = 0; i < 4; i++)
            #pragma unroll
            for (int jj = 0; jj < 4; jj++)
                #pragma unroll
                for (int r = 0; r < 4; r++) acc[i][jj][r] = 0.f;

        auto issue = [&](int st, int kb) {
            const uint32_t dbase = smaddr + (uint32_t)st * 32768u + tid * 32u;
            const size_t ko = (size_t)kb * 2048 + tid * 8;
            CP16(dbase,          aoh + abase + ko);
            CP16(dbase + 16,     aoh + abase + ko + 4);
            CP16(dbase + 8192,   aol + abase + ko);
            CP16(dbase + 8208,   aol + abase + ko + 4);
            CP16(dbase + 16384,  Woh + bbase + ko);
            CP16(dbase + 16400,  Woh + bbase + ko + 4);
            CP16(dbase + 24576,  Wol + bbase + ko);
            CP16(dbase + 24592,  Wol + bbase + ko + 4);
            asm volatile("cp.async.commit_group;" ::: "memory");
        };

        issue(0, 0);

        for (int kb = 0; kb < 32; kb++) {
            asm volatile("cp.async.wait_group 0;" ::: "memory");
            __syncthreads();
            if (kb < 31) issue((kb + 1) & 1, kb + 1);

            const uint32_t* As = sm + (kb & 1) * 8192;
            const uint32_t* Bs = As + 4096;

            #pragma unroll
            for (int kt2 = 0; kt2 < 2; kt2++) {
                uint4 Afh[4], Afl[4];
                uint4 Bh4[2], Bl4[2];
                const uint32_t* pa_ = &As[(kt2 * 8 + wm * 4) * 128 + lane * 4];
                #pragma unroll
                for (int i = 0; i < 4; i++) {
                    Afh[i] = *(const uint4*)(pa_ + i * 128);
                    Afl[i] = *(const uint4*)(pa_ + 2048 + i * 128);
                }
                const uint32_t* pb_ = &Bs[(kt2 * 8 + wn * 2) * 128 + lane * 4];
                #pragma unroll
                for (int i = 0; i < 2; i++) {
                    Bh4[i] = *(const uint4*)(pb_ + i * 128);
                    Bl4[i] = *(const uint4*)(pb_ + 2048 + i * 128);
                }
                #pragma unroll
                for (int mt = 0; mt < 4; mt++)
                    #pragma unroll
                    for (int nt = 0; nt < 4; nt++) {
                        const uint32_t* bh = (const uint32_t*)&Bh4[nt >> 1] + (nt & 1) * 2;
                        const uint32_t* bl = (const uint32_t*)&Bl4[nt >> 1] + (nt & 1) * 2;
                        mma16816(acc[mt][nt], (const uint32_t*)&Afh[mt], bh);
                        mma16816(acc[mt][nt], (const uint32_t*)&Afh[mt], bl);
                        mma16816(acc[mt][nt], (const uint32_t*)&Afl[mt], bh);
                    }
            }
        }

        #pragma unroll
        for (int mt = 0; mt < 4; mt++) {
            #pragma unroll
            for (int nt = 0; nt < 4; nt++) {
                const int m = m0 + wm * 64 + mt * 16 + (lane >> 2);
                const int n = n0 + wn * 32 + nt * 8 + ((lane & 3) << 1);
                const float* c = acc[mt][nt];
                *(float2*)&C[(size_t)m * 1024 + n]       = make_float2(c[0], c[1]);
                *(float2*)&C[(size_t)(m + 8) * 1024 + n] = make_float2(c[2], c[3]);
            }
        }
    }
}

// ---------------------------------------------------------------------------
extern "C" void kernel_launch(void* const* d_in, const int* in_sizes, int n_in,
                              void* d_out, int out_size) {
    const float* x  = (const float*)d_in[0];
    const float* wq = (const float*)d_in[1];
    const float* wk = (const float*)d_in[2];
    const float* wv = (const float*)d_in[3];
    const float* wo = (const float*)d_in[4];
    const float* fc = (const float*)d_in[5];
    float* out = (float*)d_out;

    uint32_t *qfhp, *qflp, *kfhp, *kflp, *vfhp, *vflp;
    uint32_t *xhp, *xlp, *aohp, *aolp;
    uint32_t *wqhp, *wqlp, *wkhp, *wklp, *wvhp, *wvlp, *wohp, *wolp;
    int* flagsp;
    cudaGetSymbolAddress((void**)&qfhp, g_qfh);
    cudaGetSymbolAddress((void**)&qflp, g_qfl);
    cudaGetSymbolAddress((void**)&kfhp, g_kfh);
    cudaGetSymbolAddress((void**)&kflp, g_kfl);
    cudaGetSymbolAddress((void**)&vfhp, g_vfh);
    cudaGetSymbolAddress((void**)&vflp, g_vfl);
    cudaGetSymbolAddress((void**)&xhp, g_xh);
    cudaGetSymbolAddress((void**)&xlp, g_xl);
    cudaGetSymbolAddress((void**)&aohp, g_aoh);
    cudaGetSymbolAddress((void**)&aolp, g_aol);
    cudaGetSymbolAddress((void**)&wqhp, g_wqh);
    cudaGetSymbolAddress((void**)&wqlp, g_wql);
    cudaGetSymbolAddress((void**)&wkhp, g_wkh);
    cudaGetSymbolAddress((void**)&wklp, g_wkl);
    cudaGetSymbolAddress((void**)&wvhp, g_wvh);
    cudaGetSymbolAddress((void**)&wvlp, g_wvl);
    cudaGetSymbolAddress((void**)&wohp, g_woh);
    cudaGetSymbolAddress((void**)&wolp, g_wol);
    cudaGetSymbolAddress((void**)&flagsp, g_flags);

    const int DYNSZ  = 65536;
    const int ADYNSZ = 81920;
    cudaFuncSetAttribute(gemm_qkv,   cudaFuncAttributeMaxDynamicSharedMemorySize, DYNSZ);
    cudaFuncSetAttribute(attn_ogemm, cudaFuncAttributeMaxDynamicSharedMemorySize, ADYNSZ);

    cudaMemsetAsync(flagsp, 0, 32 * sizeof(int));

    const int xpairs = M_ROWS * 512;
    const int wpairs = DD * 512;
    split_permA<<<(xpairs + 255) / 256, 256>>>((const float2*)x, xhp, xlp, xpairs);
    dim3 sgrid((wpairs + 255) / 256, 4);
    split_permB4<<<sgrid, 256>>>((const float2*)wq, (const float2*)wk,
                                 (const float2*)wv, (const float2*)wo,
                                 wqhp, wqlp, wkhp, wklp, wvhp, wvlp, wohp, wolp,
                                 wpairs);

    dim3 qkvgrid(24, M_ROWS / 128);   // (24, 32)
    gemm_qkv<<<qkvgrid, 256, DYNSZ>>>(xhp, xlp, wqhp, wqlp, wkhp, wklp, wvhp, wvlp,
                                      (const float2*)fc, qfhp, qflp, kfhp, kflp,
                                      vfhp, vflp);

    attn_ogemm<<<768, 256, ADYNSZ>>>(qfhp, qflp, kfhp, kflp, vfhp, vflp,
                                     aohp, aolp, wohp, wolp, out);
}

// round 16
// speedup vs baseline: 1.0312x; 1.0099x over previous
#include <cuda_runtime.h>
#include <cuda_bf16.h>
#include <cstdint>

#define BB 2
#define TT 2048
#define DD 1024
#define HH 16
#define HD 64
#define M_ROWS (BB*TT)   // 4096

// ---------------------------------------------------------------------------
// Device scratch (allocation-free). Fragment-image layouts; B-side PAIRED:
// two adjacent n-tiles' fragments per lane are contiguous (one LDS.128).
// ---------------------------------------------------------------------------
__device__ uint32_t g_qfh[BB*HH*16*4096];    // Q A-frag image per 128-row block
__device__ uint32_t g_qfl[BB*HH*16*4096];
__device__ uint32_t g_kfh[BB*HH*32*2048];    // K B-frag image per 64-key tile
__device__ uint32_t g_kfl[BB*HH*32*2048];
__device__ uint32_t g_vfh[BB*HH*32*2048];    // V B-frag image per 64-key tile
__device__ uint32_t g_vfl[BB*HH*32*2048];
__device__ uint32_t g_xh[M_ROWS*512];        // x, A-perm
__device__ uint32_t g_xl[M_ROWS*512];
__device__ uint32_t g_wqh[DD*512], g_wql[DD*512];   // weights, B-perm (paired)
__device__ uint32_t g_wkh[DD*512], g_wkl[DD*512];
__device__ uint32_t g_wvh[DD*512], g_wvl[DD*512];
__device__ uint32_t g_woh[DD*512], g_wol[DD*512];
__device__ uint32_t g_aoh[M_ROWS*512];       // attn out, A-perm
__device__ uint32_t g_aol[M_ROWS*512];

// ---------------------------------------------------------------------------
// helpers
// ---------------------------------------------------------------------------
__device__ __forceinline__ uint32_t smem_u32(const void* p) {
    return (uint32_t)__cvta_generic_to_shared(p);
}

#define CP16(d, s) asm volatile("cp.async.cg.shared.global [%0], [%1], 16;" \
                                :: "r"(d), "l"(s) : "memory")

__device__ __forceinline__ void mma16816(float* c, const uint32_t* a, const uint32_t* b) {
    asm volatile(
        "mma.sync.aligned.m16n8k16.row.col.f32.bf16.bf16.f32 "
        "{%0,%1,%2,%3}, {%4,%5,%6,%7}, {%8,%9}, {%0,%1,%2,%3};"
        : "+f"(c[0]), "+f"(c[1]), "+f"(c[2]), "+f"(c[3])
        : "r"(a[0]), "r"(a[1]), "r"(a[2]), "r"(a[3]), "r"(b[0]), "r"(b[1]));
}

__device__ __forceinline__ float ex2f(float x) {
    float y; asm("ex2.approx.f32 %0, %1;" : "=f"(y) : "f"(x)); return y;
}

__device__ __forceinline__ uint32_t split_pair(float a, float b, uint32_t& lo) {
    __nv_bfloat162 h = __floats2bfloat162_rn(a, b);
    float ra = a - __bfloat162float(h.x);
    float rb = b - __bfloat162float(h.y);
    __nv_bfloat162 l = __floats2bfloat162_rn(ra, rb);
    lo = *reinterpret_cast<uint32_t*>(&l);
    return *reinterpret_cast<uint32_t*>(&h);
}

// A-perm index: (m row 0..4095, kp pair 0..511) -> fragment-image slot
__device__ __forceinline__ size_t apermidx(int m, int kp) {
    const int mb = m >> 7, r = m & 127;
    const int kb = kp >> 4, kr = kp & 15;
    const int kt = kr >> 3, khalf = (kr >> 2) & 1, j = kr & 3;
    const int tile = kt * 8 + (r >> 4);
    const int lane = (r & 7) * 4 + j;
    const int areg = ((r >> 3) & 1) | (khalf << 1);
    return ((size_t)(mb * 32 + kb)) * 2048 + tile * 128 + lane * 4 + areg;
}
// B-perm index (PAIRED): (n row, kp pair) -> fragment-image slot
__device__ __forceinline__ size_t bpermidx(int n, int kp) {
    const int nb = n >> 7, r = n & 127;
    const int kb = kp >> 4, kr = kp & 15;
    const int kt = kr >> 3, khalf = (kr >> 2) & 1, j = kr & 3;
    const int ntile = r >> 3;
    const int lane = (r & 7) * 4 + j;
    return ((size_t)(nb * 32 + kb)) * 2048 +
           (kt * 8 + (ntile >> 1)) * 128 + lane * 4 + (ntile & 1) * 2 + khalf;
}
// Q-frag slot for (bh, t, pair i)
__device__ __forceinline__ size_t qfragidx(int bh, int t, int i) {
    const int ks = i >> 3, kk2 = i & 7;
    const int c2 = kk2 & 3, khalf = kk2 >> 2;
    const int row = t & 127, qb = t >> 7;
    const int wq = row >> 4, wrow = row & 15;
    const int areg = ((wrow >> 3) & 1) | (khalf << 1);
    return (size_t)bh * 65536 + qb * 4096 +
           ((wq * 4 + ks) * 32 + (wrow & 7) * 4 + c2) * 4 + areg;
}
// K-frag slot (PAIRED) for (bh, t, pair i)
__device__ __forceinline__ size_t kfragidx(int bh, int t, int i) {
    const int ks = i >> 3, kk2 = i & 7;
    const int c2 = kk2 & 3, khalf = kk2 >> 2;
    const int key = t & 63, ktile = t >> 6;
    const int ntile = key >> 3;
    const int lane = (key & 7) * 4 + c2;
    return (size_t)bh * 65536 + ktile * 2048 +
           (ks * 4 + (ntile >> 1)) * 128 + lane * 4 + (ntile & 1) * 2 + khalf;
}

// ---------------------------------------------------------------------------
// splits (two right-sized launches)
// ---------------------------------------------------------------------------
__global__ void split_permA(const float2* __restrict__ src,
                            uint32_t* __restrict__ dh, uint32_t* __restrict__ dl,
                            int total) {
    int i = blockIdx.x * blockDim.x + threadIdx.x;
    if (i >= total) return;
    float2 v = src[i];
    uint32_t lo, hi = split_pair(v.x, v.y, lo);
    const size_t idx = apermidx(i >> 9, i & 511);
    dh[idx] = hi; dl[idx] = lo;
}
__global__ void split_permB4(const float2* __restrict__ s0, const float2* __restrict__ s1,
                             const float2* __restrict__ s2, const float2* __restrict__ s3,
                             uint32_t* __restrict__ h0, uint32_t* __restrict__ l0,
                             uint32_t* __restrict__ h1, uint32_t* __restrict__ l1,
                             uint32_t* __restrict__ h2, uint32_t* __restrict__ l2,
                             uint32_t* __restrict__ h3, uint32_t* __restrict__ l3,
                             int total) {
    int i = blockIdx.x * blockDim.x + threadIdx.x;
    if (i >= total) return;
    const int which = blockIdx.y;
    const float2* src = which == 0 ? s0 : which == 1 ? s1 : which == 2 ? s2 : s3;
    uint32_t* dh = which == 0 ? h0 : which == 1 ? h1 : which == 2 ? h2 : h3;
    uint32_t* dl = which == 0 ? l0 : which == 1 ? l1 : which == 2 ? l2 : l3;
    float2 v = src[i];
    uint32_t lo, hi = split_pair(v.x, v.y, lo);
    const size_t idx = bpermidx(i >> 9, i & 511);
    dh[idx] = hi; dl[idx] = lo;
}

// ---------------------------------------------------------------------------
// Fused QKV GEMM (grid.x = 24: 8 n-blocks x {Q,K,V}). 256 threads, warp 64x32.
// Q is pre-scaled by 0.125*log2(e) so attention softmax runs in log2 domain.
// ---------------------------------------------------------------------------
#define QSCALE 0.18033688011112042f   // 0.125 * log2(e)

__global__ __launch_bounds__(256, 2)
void gemm_qkv(const uint32_t* __restrict__ Ah, const uint32_t* __restrict__ Al,
              const uint32_t* __restrict__ Wqh, const uint32_t* __restrict__ Wql,
              const uint32_t* __restrict__ Wkh, const uint32_t* __restrict__ Wkl,
              const uint32_t* __restrict__ Wvh, const uint32_t* __restrict__ Wvl,
              const float2* __restrict__ fc2,
              uint32_t* __restrict__ qfh, uint32_t* __restrict__ qfl,
              uint32_t* __restrict__ kfh, uint32_t* __restrict__ kfl,
              uint32_t* __restrict__ vfh, uint32_t* __restrict__ vfl) {
    extern __shared__ __align__(16) uint32_t sm[];   // 64KB

    const int which = blockIdx.x >> 3;               // 0=Q 1=K 2=V
    const int nblk  = blockIdx.x & 7;
    const uint32_t* Wh = which == 0 ? Wqh : which == 1 ? Wkh : Wvh;
    const uint32_t* Wl = which == 0 ? Wql : which == 1 ? Wkl : Wvl;

    const int tid  = threadIdx.x;
    const int lane = tid & 31;
    const int w    = tid >> 5;
    const int wm   = w & 1;
    const int wn   = w >> 1;
    const int m0   = blockIdx.y * 128;
    const int n0   = nblk * 128;
    const size_t abase = ((size_t)blockIdx.y * 32) * 2048;
    const size_t bbase = ((size_t)nblk * 32) * 2048;
    const uint32_t smaddr = smem_u32(sm);

    float acc[4][4][4];
    #pragma unroll
    for (int i = 0; i < 4; i++)
        #pragma unroll
        for (int j = 0; j < 4; j++)
            #pragma unroll
            for (int r = 0; r < 4; r++) acc[i][j][r] = 0.f;

    auto issue = [&](int st, int kb) {
        const uint32_t dbase = smaddr + (uint32_t)st * 32768u + tid * 32u;
        const size_t ko = (size_t)kb * 2048 + tid * 8;
        CP16(dbase,          Ah + abase + ko);
        CP16(dbase + 16,     Ah + abase + ko + 4);
        CP16(dbase + 8192,   Al + abase + ko);
        CP16(dbase + 8208,   Al + abase + ko + 4);
        CP16(dbase + 16384,  Wh + bbase + ko);
        CP16(dbase + 16400,  Wh + bbase + ko + 4);
        CP16(dbase + 24576,  Wl + bbase + ko);
        CP16(dbase + 24592,  Wl + bbase + ko + 4);
        asm volatile("cp.async.commit_group;" ::: "memory");
    };

    issue(0, 0);

    for (int kb = 0; kb < 32; kb++) {
        asm volatile("cp.async.wait_group 0;" ::: "memory");
        __syncthreads();
        if (kb < 31) issue((kb + 1) & 1, kb + 1);

        const uint32_t* As = sm + (kb & 1) * 8192;
        const uint32_t* Bs = As + 4096;

        #pragma unroll
        for (int kt2 = 0; kt2 < 2; kt2++) {
            uint4 Afh[4], Afl[4];
            uint4 Bh4[2], Bl4[2];
            const uint32_t* pa_ = &As[(kt2 * 8 + wm * 4) * 128 + lane * 4];
            #pragma unroll
            for (int i = 0; i < 4; i++) {
                Afh[i] = *(const uint4*)(pa_ + i * 128);
                Afl[i] = *(const uint4*)(pa_ + 2048 + i * 128);
            }
            const uint32_t* pb_ = &Bs[(kt2 * 8 + wn * 2) * 128 + lane * 4];
            #pragma unroll
            for (int i = 0; i < 2; i++) {
                Bh4[i] = *(const uint4*)(pb_ + i * 128);
                Bl4[i] = *(const uint4*)(pb_ + 2048 + i * 128);
            }
            #pragma unroll
            for (int mt = 0; mt < 4; mt++)
                #pragma unroll
                for (int nt = 0; nt < 4; nt++) {
                    const uint32_t* bh = (const uint32_t*)&Bh4[nt >> 1] + (nt & 1) * 2;
                    const uint32_t* bl = (const uint32_t*)&Bl4[nt >> 1] + (nt & 1) * 2;
                    mma16816(acc[mt][nt], (const uint32_t*)&Afh[mt], bh);
                    mma16816(acc[mt][nt], (const uint32_t*)&Afh[mt], bl);
                    mma16816(acc[mt][nt], (const uint32_t*)&Afl[mt], bh);
                }
        }
    }

    // epilogue
    #pragma unroll
    for (int mt = 0; mt < 4; mt++) {
        #pragma unroll
        for (int nt = 0; nt < 4; nt++) {
            const int m = m0 + wm * 64 + mt * 16 + (lane >> 2);
            const int n = n0 + wn * 32 + nt * 8 + ((lane & 3) << 1);
            float* c = acc[mt][nt];
            const int b = m >> 11, t = m & 2047;
            const int h = n >> 6,  d = n & 63;
            const int bh = b * HH + h;
            if (which < 2) {
                const int i = d >> 1;
                #pragma unroll
                for (int rr = 0; rr < 2; rr++) {
                    const int tt = t + rr * 8;
                    const float2 cs = fc2[tt * 32 + i];
                    float o0 = c[rr*2] * cs.x - c[rr*2+1] * cs.y;
                    float o1 = c[rr*2] * cs.y + c[rr*2+1] * cs.x;
                    uint32_t lo, hi;
                    if (which == 0) {
                        hi = split_pair(o0 * QSCALE, o1 * QSCALE, lo);
                        const size_t qi = qfragidx(bh, tt, i);
                        qfh[qi] = hi; qfl[qi] = lo;
                    } else {
                        hi = split_pair(o0, o1, lo);
                        const size_t ki = kfragidx(bh, tt, i);
                        kfh[ki] = hi; kfl[ki] = lo;
                    }
                }
            } else {
                #pragma unroll
                for (int rr = 0; rr < 2; rr++) {
                    const int tt = t + rr * 8;
                    const int kt3 = tt >> 6, kpp = (tt & 63) >> 1, hf = tt & 1;
                    const int ks3 = kpp >> 3, kk3 = kpp & 7;
                    const int c3 = kk3 & 3, kh3 = kk3 >> 2;
                    #pragma unroll
                    for (int jj = 0; jj < 2; jj++) {
                        const int dd = d + jj;
                        const int ntile = dd >> 3;
                        const int vlane = (dd & 7) * 4 + c3;
                        const int slot = (ks3 * 4 + (ntile >> 1)) * 128 +
                                         vlane * 4 + (ntile & 1) * 2 + kh3;
                        const size_t u32i = (size_t)bh * 65536 + kt3 * 2048 + slot;
                        const float v = c[rr * 2 + jj];
                        __nv_bfloat16 hb = __float2bfloat16_rn(v);
                        __nv_bfloat16 lb = __float2bfloat16_rn(v - __bfloat162float(hb));
                        ((uint16_t*)vfh)[u32i * 2 + hf] = *(uint16_t*)&hb;
                        ((uint16_t*)vfl)[u32i * 2 + hf] = *(uint16_t*)&lb;
                    }
                }
            }
        }
    }
}

// ---------------------------------------------------------------------------
// O-projection GEMM (A-perm x B-perm -> fp32 row-major out). 256 threads.
// ---------------------------------------------------------------------------
__global__ __launch_bounds__(256, 2)
void gemm_o(const uint32_t* __restrict__ Ah, const uint32_t* __restrict__ Al,
            const uint32_t* __restrict__ Wh, const uint32_t* __restrict__ Wl,
            float* __restrict__ C) {
    extern __shared__ __align__(16) uint32_t sm[];

    const int tid  = threadIdx.x;
    const int lane = tid & 31;
    const int w    = tid >> 5;
    const int wm   = w & 1;
    const int wn   = w >> 1;
    const int m0   = blockIdx.y * 128;
    const int n0   = blockIdx.x * 128;
    const size_t abase = ((size_t)blockIdx.y * 32) * 2048;
    const size_t bbase = ((size_t)blockIdx.x * 32) * 2048;
    const uint32_t smaddr = smem_u32(sm);

    float acc[4][4][4];
    #pragma unroll
    for (int i = 0; i < 4; i++)
        #pragma unroll
        for (int j = 0; j < 4; j++)
            #pragma unroll
            for (int r = 0; r < 4; r++) acc[i][j][r] = 0.f;

    auto issue = [&](int st, int kb) {
        const uint32_t dbase = smaddr + (uint32_t)st * 32768u + tid * 32u;
        const size_t ko = (size_t)kb * 2048 + tid * 8;
        CP16(dbase,          Ah + abase + ko);
        CP16(dbase + 16,     Ah + abase + ko + 4);
        CP16(dbase + 8192,   Al + abase + ko);
        CP16(dbase + 8208,   Al + abase + ko + 4);
        CP16(dbase + 16384,  Wh + bbase + ko);
        CP16(dbase + 16400,  Wh + bbase + ko + 4);
        CP16(dbase + 24576,  Wl + bbase + ko);
        CP16(dbase + 24592,  Wl + bbase + ko + 4);
        asm volatile("cp.async.commit_group;" ::: "memory");
    };

    issue(0, 0);

    for (int kb = 0; kb < 32; kb++) {
        asm volatile("cp.async.wait_group 0;" ::: "memory");
        __syncthreads();
        if (kb < 31) issue((kb + 1) & 1, kb + 1);

        const uint32_t* As = sm + (kb & 1) * 8192;
        const uint32_t* Bs = As + 4096;

        #pragma unroll
        for (int kt2 = 0; kt2 < 2; kt2++) {
            uint4 Afh[4], Afl[4];
            uint4 Bh4[2], Bl4[2];
            const uint32_t* pa_ = &As[(kt2 * 8 + wm * 4) * 128 + lane * 4];
            #pragma unroll
            for (int i = 0; i < 4; i++) {
                Afh[i] = *(const uint4*)(pa_ + i * 128);
                Afl[i] = *(const uint4*)(pa_ + 2048 + i * 128);
            }
            const uint32_t* pb_ = &Bs[(kt2 * 8 + wn * 2) * 128 + lane * 4];
            #pragma unroll
            for (int i = 0; i < 2; i++) {
                Bh4[i] = *(const uint4*)(pb_ + i * 128);
                Bl4[i] = *(const uint4*)(pb_ + 2048 + i * 128);
            }
            #pragma unroll
            for (int mt = 0; mt < 4; mt++)
                #pragma unroll
                for (int nt = 0; nt < 4; nt++) {
                    const uint32_t* bh = (const uint32_t*)&Bh4[nt >> 1] + (nt & 1) * 2;
                    const uint32_t* bl = (const uint32_t*)&Bl4[nt >> 1] + (nt & 1) * 2;
                    mma16816(acc[mt][nt], (const uint32_t*)&Afh[mt], bh);
                    mma16816(acc[mt][nt], (const uint32_t*)&Afh[mt], bl);
                    mma16816(acc[mt][nt], (const uint32_t*)&Afl[mt], bh);
                }
        }
    }

    #pragma unroll
    for (int mt = 0; mt < 4; mt++) {
        #pragma unroll
        for (int nt = 0; nt < 4; nt++) {
            const int m = m0 + wm * 64 + mt * 16 + (lane >> 2);
            const int n = n0 + wn * 32 + nt * 8 + ((lane & 3) << 1);
            const float* c = acc[mt][nt];
            *(float2*)&C[(size_t)m * 1024 + n]       = make_float2(c[0], c[1]);
            *(float2*)&C[(size_t)(m + 8) * 1024 + n] = make_float2(c[2], c[3]);
        }
    }
}

// ---------------------------------------------------------------------------
// Tensor-core flash attention (mma.sync, causal, log2-domain softmax).
// 1D grid heavy-first. 2 CTAs/SM. Paired K/V B-frag images (LDS.128 loads).
// smem: [2 stages x 8192 u32][Q-lo 4096 u32] = 80KB.
// ---------------------------------------------------------------------------
__global__ __launch_bounds__(256, 2)
void attn_mma(const uint32_t* __restrict__ qfh, const uint32_t* __restrict__ qfl,
              const uint32_t* __restrict__ kfh, const uint32_t* __restrict__ kfl,
              const uint32_t* __restrict__ vfh, const uint32_t* __restrict__ vfl,
              uint32_t* __restrict__ aoh, uint32_t* __restrict__ aol) {
    extern __shared__ __align__(16) uint32_t sm[];
    const int qi = 15 - (blockIdx.x >> 5);
    const int bh = blockIdx.x & 31;
    const int b  = bh >> 4, hhd = bh & 15;
    const int q0 = qi * 128;
    const int tid = threadIdx.x;
    const int lane = tid & 31;
    const int w = tid >> 5;
    const uint32_t smaddr = smem_u32(sm);
    const size_t hbase = (size_t)bh * 65536;
    uint32_t* qlo_s = sm + 16384;

    uint4 qfh_r[4];
    {
        const size_t qb = hbase + (size_t)qi * 4096;
        #pragma unroll
        for (int ks = 0; ks < 4; ks++) {
            const size_t o = qb + ((w * 4 + ks) * 32 + lane) * 4;
            qfh_r[ks] = *(const uint4*)&qfh[o];
        }
        #pragma unroll
        for (int i = 0; i < 4; i++) {
            const int id = i * 1024 + tid * 4;
            *(uint4*)&qlo_s[id] = *(const uint4*)&qfl[qb + id];
        }
    }
    __syncthreads();

    float oacc[8][4];
    #pragma unroll
    for (int dt = 0; dt < 8; dt++)
        #pragma unroll
        for (int r = 0; r < 4; r++) oacc[dt][r] = 0.f;
    float mr0 = -1e30f, mr1 = -1e30f, lr0 = 0.f, lr1 = 0.f;

    const int r0 = q0 + w * 16;
    const int ntiles = qi * 2 + 2;

    auto issue = [&](int st, int kt) {
        const uint32_t dbase = smaddr + (uint32_t)st * 32768u + tid * 32u;
        const size_t ko = hbase + (size_t)kt * 2048 + tid * 8;
        CP16(dbase,          kfh + ko);
        CP16(dbase + 16,     kfh + ko + 4);
        CP16(dbase + 8192,   kfl + ko);
        CP16(dbase + 8208,   kfl + ko + 4);
        CP16(dbase + 16384,  vfh + ko);
        CP16(dbase + 16400,  vfh + ko + 4);
        CP16(dbase + 24576,  vfl + ko);
        CP16(dbase + 24592,  vfl + ko + 4);
        asm volatile("cp.async.commit_group;" ::: "memory");
    };

    issue(0, 0);

    for (int kt = 0; kt < ntiles; kt++) {
        const int kt0 = kt * 64;
        asm volatile("cp.async.wait_group 0;" ::: "memory");
        __syncthreads();
        if (kt + 1 < ntiles) issue((kt + 1) & 1, kt + 1);

        const uint32_t* S = sm + (kt & 1) * 8192;

        if (kt0 <= r0 + 15) {
            float sacc[8][4];
            #pragma unroll
            for (int nt = 0; nt < 8; nt++)
                #pragma unroll
                for (int r = 0; r < 4; r++) sacc[nt][r] = 0.f;
            #pragma unroll
            for (int ks = 0; ks < 4; ks++) {
                const uint4 qlo = *(const uint4*)&qlo_s[((w * 4 + ks) * 32 + lane) * 4];
                #pragma unroll
                for (int p = 0; p < 4; p++) {
                    const uint4 kh4 = *(const uint4*)&S[(ks * 4 + p) * 128 + lane * 4];
                    const uint4 kl4 = *(const uint4*)&S[2048 + (ks * 4 + p) * 128 + lane * 4];
                    #pragma unroll
                    for (int hh = 0; hh < 2; hh++) {
                        const int nt = p * 2 + hh;
                        const uint32_t* kbh = (const uint32_t*)&kh4 + hh * 2;
                        const uint32_t* kbl = (const uint32_t*)&kl4 + hh * 2;
                        mma16816(sacc[nt], (const uint32_t*)&qfh_r[ks], kbh);
                        mma16816(sacc[nt], (const uint32_t*)&qfh_r[ks], kbl);
                        mma16816(sacc[nt], (const uint32_t*)&qlo, kbh);
                    }
                }
            }
            if (kt0 + 63 > r0) {
                const int colb = kt0 + ((lane & 3) << 1);
                const int rowb = r0 + (lane >> 2);
                #pragma unroll
                for (int nt = 0; nt < 8; nt++) {
                    #pragma unroll
                    for (int r = 0; r < 4; r++) {
                        const int col = colb + nt * 8 + (r & 1);
                        const int row = rowb + ((r >> 1) << 3);
                        if (col > row) sacc[nt][r] = -1e30f;
                    }
                }
            }
            float mx0 = -1e30f, mx1 = -1e30f;
            #pragma unroll
            for (int nt = 0; nt < 8; nt++) {
                mx0 = fmaxf(mx0, fmaxf(sacc[nt][0], sacc[nt][1]));
                mx1 = fmaxf(mx1, fmaxf(sacc[nt][2], sacc[nt][3]));
            }
            mx0 = fmaxf(mx0, __shfl_xor_sync(0xffffffffu, mx0, 1));
            mx0 = fmaxf(mx0, __shfl_xor_sync(0xffffffffu, mx0, 2));
            mx1 = fmaxf(mx1, __shfl_xor_sync(0xffffffffu, mx1, 1));
            mx1 = fmaxf(mx1, __shfl_xor_sync(0xffffffffu, mx1, 2));
            const float mn0 = fmaxf(mr0, mx0);
            const float mn1 = fmaxf(mr1, mx1);
            const float corr0 = ex2f(mr0 - mn0);
            const float corr1 = ex2f(mr1 - mn1);
            mr0 = mn0; mr1 = mn1;
            float s0 = 0.f, s1 = 0.f;
            #pragma unroll
            for (int nt = 0; nt < 8; nt++) {
                sacc[nt][0] = ex2f(sacc[nt][0] - mn0);
                sacc[nt][1] = ex2f(sacc[nt][1] - mn0);
                sacc[nt][2] = ex2f(sacc[nt][2] - mn1);
                sacc[nt][3] = ex2f(sacc[nt][3] - mn1);
                s0 += sacc[nt][0] + sacc[nt][1];
                s1 += sacc[nt][2] + sacc[nt][3];
            }
            lr0 = lr0 * corr0 + s0;
            lr1 = lr1 * corr1 + s1;
            #pragma unroll
            for (int dt = 0; dt < 8; dt++) {
                oacc[dt][0] *= corr0; oacc[dt][1] *= corr0;
                oacc[dt][2] *= corr1; oacc[dt][3] *= corr1;
            }
            uint32_t pah[4][4], pal[4][4];
            #pragma unroll
            for (int ksp = 0; ksp < 4; ksp++) {
                pah[ksp][0] = split_pair(sacc[2*ksp][0],   sacc[2*ksp][1],   pal[ksp][0]);
                pah[ksp][1] = split_pair(sacc[2*ksp][2],   sacc[2*ksp][3],   pal[ksp][1]);
                pah[ksp][2] = split_pair(sacc[2*ksp+1][0], sacc[2*ksp+1][1], pal[ksp][2]);
                pah[ksp][3] = split_pair(sacc[2*ksp+1][2], sacc[2*ksp+1][3], pal[ksp][3]);
            }
            #pragma unroll
            for (int ksp = 0; ksp < 4; ksp++) {
                #pragma unroll
                for (int p = 0; p < 4; p++) {
                    const uint4 vh4 = *(const uint4*)&S[4096 + (ksp * 4 + p) * 128 + lane * 4];
                    const uint4 vl4 = *(const uint4*)&S[6144 + (ksp * 4 + p) * 128 + lane * 4];
                    #pragma unroll
                    for (int hh = 0; hh < 2; hh++) {
                        const int dt = p * 2 + hh;
                        const uint32_t* vbh = (const uint32_t*)&vh4 + hh * 2;
                        const uint32_t* vbl = (const uint32_t*)&vl4 + hh * 2;
                        mma16816(oacc[dt], pah[ksp], vbh);
                        mma16816(oacc[dt], pal[ksp], vbh);
                        mma16816(oacc[dt], pah[ksp], vbl);
                    }
                }
            }
        }
    }

    lr0 += __shfl_xor_sync(0xffffffffu, lr0, 1);
    lr0 += __shfl_xor_sync(0xffffffffu, lr0, 2);
    lr1 += __shfl_xor_sync(0xffffffffu, lr1, 1);
    lr1 += __shfl_xor_sync(0xffffffffu, lr1, 2);
    const float inv0 = 1.f / lr0;
    const float inv1 = 1.f / lr1;
    const int t0 = r0 + (lane >> 2);
    const int t1 = t0 + 8;
    #pragma unroll
    for (int dt = 0; dt < 8; dt++) {
        const int kp = hhd * 32 + dt * 4 + (lane & 3);
        uint32_t lo;
        uint32_t hi = split_pair(oacc[dt][0] * inv0, oacc[dt][1] * inv0, lo);
        const size_t i0 = apermidx(b * TT + t0, kp);
        aoh[i0] = hi; aol[i0] = lo;
        hi = split_pair(oacc[dt][2] * inv1, oacc[dt][3] * inv1, lo);
        const size_t i1 = apermidx(b * TT + t1, kp);
        aoh[i1] = hi; aol[i1] = lo;
    }
}

// ---------------------------------------------------------------------------
extern "C" void kernel_launch(void* const* d_in, const int* in_sizes, int n_in,
                              void* d_out, int out_size) {
    const float* x  = (const float*)d_in[0];
    const float* wq = (const float*)d_in[1];
    const float* wk = (const float*)d_in[2];
    const float* wv = (const float*)d_in[3];
    const float* wo = (const float*)d_in[4];
    const float* fc = (const float*)d_in[5];
    float* out = (float*)d_out;

    uint32_t *qfhp, *qflp, *kfhp, *kflp, *vfhp, *vflp;
    uint32_t *xhp, *xlp, *aohp, *aolp;
    uint32_t *wqhp, *wqlp, *wkhp, *wklp, *wvhp, *wvlp, *wohp, *wolp;
    cudaGetSymbolAddress((void**)&qfhp, g_qfh);
    cudaGetSymbolAddress((void**)&qflp, g_qfl);
    cudaGetSymbolAddress((void**)&kfhp, g_kfh);
    cudaGetSymbolAddress((void**)&kflp, g_kfl);
    cudaGetSymbolAddress((void**)&vfhp, g_vfh);
    cudaGetSymbolAddress((void**)&vflp, g_vfl);
    cudaGetSymbolAddress((void**)&xhp, g_xh);
    cudaGetSymbolAddress((void**)&xlp, g_xl);
    cudaGetSymbolAddress((void**)&aohp, g_aoh);
    cudaGetSymbolAddress((void**)&aolp, g_aol);
    cudaGetSymbolAddress((void**)&wqhp, g_wqh);
    cudaGetSymbolAddress((void**)&wqlp, g_wql);
    cudaGetSymbolAddress((void**)&wkhp, g_wkh);
    cudaGetSymbolAddress((void**)&wklp, g_wkl);
    cudaGetSymbolAddress((void**)&wvhp, g_wvh);
    cudaGetSymbolAddress((void**)&wvlp, g_wvl);
    cudaGetSymbolAddress((void**)&wohp, g_woh);
    cudaGetSymbolAddress((void**)&wolp, g_wol);

    const int DYNSZ  = 65536;
    const int ADYNSZ = 81920;
    cudaFuncSetAttribute(gemm_qkv, cudaFuncAttributeMaxDynamicSharedMemorySize, DYNSZ);
    cudaFuncSetAttribute(gemm_o,   cudaFuncAttributeMaxDynamicSharedMemorySize, DYNSZ);
    cudaFuncSetAttribute(attn_mma, cudaFuncAttributeMaxDynamicSharedMemorySize, ADYNSZ);

    const int xpairs = M_ROWS * 512;
    const int wpairs = DD * 512;
    split_permA<<<(xpairs + 255) / 256, 256>>>((const float2*)x, xhp, xlp, xpairs);
    dim3 sgrid((wpairs + 255) / 256, 4);
    split_permB4<<<sgrid, 256>>>((const float2*)wq, (const float2*)wk,
                                 (const float2*)wv, (const float2*)wo,
                                 wqhp, wqlp, wkhp, wklp, wvhp, wvlp, wohp, wolp,
                                 wpairs);

    dim3 qkvgrid(24, M_ROWS / 128);   // (24, 32)
    gemm_qkv<<<qkvgrid, 256, DYNSZ>>>(xhp, xlp, wqhp, wqlp, wkhp, wklp, wvhp, wvlp,
                                      (const float2*)fc, qfhp, qflp, kfhp, kflp,
                                      vfhp, vflp);

    attn_mma<<<512, 256, ADYNSZ>>>(qfhp, qflp, kfhp, kflp, vfhp, vflp, aohp, aolp);

    dim3 ogrid(DD / 128, M_ROWS / 128);
    gemm_o<<<ogrid, 256, DYNSZ>>>(aohp, aolp, wohp, wolp, out);
}

// round 17
// speedup vs baseline: 1.0356x; 1.0042x over previous
#include <cuda_runtime.h>
#include <cuda_bf16.h>
#include <cstdint>

#define BB 2
#define TT 2048
#define DD 1024
#define HH 16
#define HD 64
#define M_ROWS (BB*TT)   // 4096

// ---------------------------------------------------------------------------
// Device scratch (allocation-free). Fragment-image layouts; B-side PAIRED:
// two adjacent n-tiles' fragments per lane are contiguous (one LDS.128).
// ---------------------------------------------------------------------------
__device__ uint32_t g_qfh[BB*HH*16*4096];    // Q A-frag image per 128-row block
__device__ uint32_t g_qfl[BB*HH*16*4096];
__device__ uint32_t g_kfh[BB*HH*32*2048];    // K B-frag image per 64-key tile
__device__ uint32_t g_kfl[BB*HH*32*2048];
__device__ uint32_t g_vfh[BB*HH*32*2048];    // V B-frag image per 64-key tile
__device__ uint32_t g_vfl[BB*HH*32*2048];
__device__ uint32_t g_xh[M_ROWS*512];        // x, A-perm
__device__ uint32_t g_xl[M_ROWS*512];
__device__ uint32_t g_wqh[DD*512], g_wql[DD*512];   // weights, B-perm (paired)
__device__ uint32_t g_wkh[DD*512], g_wkl[DD*512];
__device__ uint32_t g_wvh[DD*512], g_wvl[DD*512];
__device__ uint32_t g_woh[DD*512], g_wol[DD*512];
__device__ uint32_t g_aoh[M_ROWS*512];       // attn out, A-perm
__device__ uint32_t g_aol[M_ROWS*512];

// ---------------------------------------------------------------------------
// helpers
// ---------------------------------------------------------------------------
__device__ __forceinline__ uint32_t smem_u32(const void* p) {
    return (uint32_t)__cvta_generic_to_shared(p);
}

#define CP16(d, s) asm volatile("cp.async.cg.shared.global [%0], [%1], 16;" \
                                :: "r"(d), "l"(s) : "memory")

__device__ __forceinline__ void mma16816(float* c, const uint32_t* a, const uint32_t* b) {
    asm volatile(
        "mma.sync.aligned.m16n8k16.row.col.f32.bf16.bf16.f32 "
        "{%0,%1,%2,%3}, {%4,%5,%6,%7}, {%8,%9}, {%0,%1,%2,%3};"
        : "+f"(c[0]), "+f"(c[1]), "+f"(c[2]), "+f"(c[3])
        : "r"(a[0]), "r"(a[1]), "r"(a[2]), "r"(a[3]), "r"(b[0]), "r"(b[1]));
}

__device__ __forceinline__ float ex2f(float x) {
    float y; asm("ex2.approx.f32 %0, %1;" : "=f"(y) : "f"(x)); return y;
}

__device__ __forceinline__ uint32_t split_pair(float a, float b, uint32_t& lo) {
    __nv_bfloat162 h = __floats2bfloat162_rn(a, b);
    float ra = a - __bfloat162float(h.x);
    float rb = b - __bfloat162float(h.y);
    __nv_bfloat162 l = __floats2bfloat162_rn(ra, rb);
    lo = *reinterpret_cast<uint32_t*>(&l);
    return *reinterpret_cast<uint32_t*>(&h);
}

// A-perm index: (m row 0..4095, kp pair 0..511) -> fragment-image slot
__device__ __forceinline__ size_t apermidx(int m, int kp) {
    const int mb = m >> 7, r = m & 127;
    const int kb = kp >> 4, kr = kp & 15;
    const int kt = kr >> 3, khalf = (kr >> 2) & 1, j = kr & 3;
    const int tile = kt * 8 + (r >> 4);
    const int lane = (r & 7) * 4 + j;
    const int areg = ((r >> 3) & 1) | (khalf << 1);
    return ((size_t)(mb * 32 + kb)) * 2048 + tile * 128 + lane * 4 + areg;
}
// B-perm index (PAIRED): (n row, kp pair) -> fragment-image slot
__device__ __forceinline__ size_t bpermidx(int n, int kp) {
    const int nb = n >> 7, r = n & 127;
    const int kb = kp >> 4, kr = kp & 15;
    const int kt = kr >> 3, khalf = (kr >> 2) & 1, j = kr & 3;
    const int ntile = r >> 3;
    const int lane = (r & 7) * 4 + j;
    return ((size_t)(nb * 32 + kb)) * 2048 +
           (kt * 8 + (ntile >> 1)) * 128 + lane * 4 + (ntile & 1) * 2 + khalf;
}
// Q-frag slot for (bh, t, pair i)
__device__ __forceinline__ size_t qfragidx(int bh, int t, int i) {
    const int ks = i >> 3, kk2 = i & 7;
    const int c2 = kk2 & 3, khalf = kk2 >> 2;
    const int row = t & 127, qb = t >> 7;
    const int wq = row >> 4, wrow = row & 15;
    const int areg = ((wrow >> 3) & 1) | (khalf << 1);
    return (size_t)bh * 65536 + qb * 4096 +
           ((wq * 4 + ks) * 32 + (wrow & 7) * 4 + c2) * 4 + areg;
}
// K-frag slot (PAIRED) for (bh, t, pair i)
__device__ __forceinline__ size_t kfragidx(int bh, int t, int i) {
    const int ks = i >> 3, kk2 = i & 7;
    const int c2 = kk2 & 3, khalf = kk2 >> 2;
    const int key = t & 63, ktile = t >> 6;
    const int ntile = key >> 3;
    const int lane = (key & 7) * 4 + c2;
    return (size_t)bh * 65536 + ktile * 2048 +
           (ks * 4 + (ntile >> 1)) * 128 + lane * 4 + (ntile & 1) * 2 + khalf;
}

// ---------------------------------------------------------------------------
// merged split: ONE launch, right-sized 1D grid.
// blocks [0, 8192)      : x -> A-perm       (8192 * 256 = 2,097,152 pairs)
// blocks [8192, 16384)  : 4 weights -> B-perm (2048 blocks = 524,288 pairs each)
// ---------------------------------------------------------------------------
__global__ void split_all(const float2* __restrict__ sx,
                          const float2* __restrict__ s1, const float2* __restrict__ s2,
                          const float2* __restrict__ s3, const float2* __restrict__ s4,
                          uint32_t* __restrict__ xh, uint32_t* __restrict__ xl,
                          uint32_t* __restrict__ h1, uint32_t* __restrict__ l1,
                          uint32_t* __restrict__ h2, uint32_t* __restrict__ l2,
                          uint32_t* __restrict__ h3, uint32_t* __restrict__ l3,
                          uint32_t* __restrict__ h4, uint32_t* __restrict__ l4) {
    const int blk = blockIdx.x;
    if (blk < 8192) {
        const int i = blk * 256 + threadIdx.x;
        float2 v = sx[i];
        uint32_t lo, hi = split_pair(v.x, v.y, lo);
        const size_t idx = apermidx(i >> 9, i & 511);
        xh[idx] = hi; xl[idx] = lo;
    } else {
        const int r = blk - 8192;
        const int which = r >> 11;            // 0..3
        const int i = (r & 2047) * 256 + threadIdx.x;
        const float2* src = which == 0 ? s1 : which == 1 ? s2 : which == 2 ? s3 : s4;
        uint32_t* dh = which == 0 ? h1 : which == 1 ? h2 : which == 2 ? h3 : h4;
        uint32_t* dl = which == 0 ? l1 : which == 1 ? l2 : which == 2 ? l3 : l4;
        float2 v = src[i];
        uint32_t lo, hi = split_pair(v.x, v.y, lo);
        const size_t idx = bpermidx(i >> 9, i & 511);
        dh[idx] = hi; dl[idx] = lo;
    }
}

// ---------------------------------------------------------------------------
// Fused QKV GEMM (grid.x = 24: 8 n-blocks x {Q,K,V}). 256 threads, warp 64x32.
// Q is pre-scaled by 0.125*log2(e) so attention softmax runs in log2 domain.
// ---------------------------------------------------------------------------
#define QSCALE 0.18033688011112042f   // 0.125 * log2(e)

__global__ __launch_bounds__(256, 2)
void gemm_qkv(const uint32_t* __restrict__ Ah, const uint32_t* __restrict__ Al,
              const uint32_t* __restrict__ Wqh, const uint32_t* __restrict__ Wql,
              const uint32_t* __restrict__ Wkh, const uint32_t* __restrict__ Wkl,
              const uint32_t* __restrict__ Wvh, const uint32_t* __restrict__ Wvl,
              const float2* __restrict__ fc2,
              uint32_t* __restrict__ qfh, uint32_t* __restrict__ qfl,
              uint32_t* __restrict__ kfh, uint32_t* __restrict__ kfl,
              uint32_t* __restrict__ vfh, uint32_t* __restrict__ vfl) {
    extern __shared__ __align__(16) uint32_t sm[];   // 64KB

    const int which = blockIdx.x >> 3;               // 0=Q 1=K 2=V
    const int nblk  = blockIdx.x & 7;
    const uint32_t* Wh = which == 0 ? Wqh : which == 1 ? Wkh : Wvh;
    const uint32_t* Wl = which == 0 ? Wql : which == 1 ? Wkl : Wvl;

    const int tid  = threadIdx.x;
    const int lane = tid & 31;
    const int w    = tid >> 5;
    const int wm   = w & 1;
    const int wn   = w >> 1;
    const int m0   = blockIdx.y * 128;
    const int n0   = nblk * 128;
    const size_t abase = ((size_t)blockIdx.y * 32) * 2048;
    const size_t bbase = ((size_t)nblk * 32) * 2048;
    const uint32_t smaddr = smem_u32(sm);

    float acc[4][4][4];
    #pragma unroll
    for (int i = 0; i < 4; i++)
        #pragma unroll
        for (int j = 0; j < 4; j++)
            #pragma unroll
            for (int r = 0; r < 4; r++) acc[i][j][r] = 0.f;

    auto issue = [&](int st, int kb) {
        const uint32_t dbase = smaddr + (uint32_t)st * 32768u + tid * 32u;
        const size_t ko = (size_t)kb * 2048 + tid * 8;
        CP16(dbase,          Ah + abase + ko);
        CP16(dbase + 16,     Ah + abase + ko + 4);
        CP16(dbase + 8192,   Al + abase + ko);
        CP16(dbase + 8208,   Al + abase + ko + 4);
        CP16(dbase + 16384,  Wh + bbase + ko);
        CP16(dbase + 16400,  Wh + bbase + ko + 4);
        CP16(dbase + 24576,  Wl + bbase + ko);
        CP16(dbase + 24592,  Wl + bbase + ko + 4);
        asm volatile("cp.async.commit_group;" ::: "memory");
    };

    issue(0, 0);

    for (int kb = 0; kb < 32; kb++) {
        asm volatile("cp.async.wait_group 0;" ::: "memory");
        __syncthreads();
        if (kb < 31) issue((kb + 1) & 1, kb + 1);

        const uint32_t* As = sm + (kb & 1) * 8192;
        const uint32_t* Bs = As + 4096;

        #pragma unroll
        for (int kt2 = 0; kt2 < 2; kt2++) {
            uint4 Afh[4], Afl[4];
            uint4 Bh4[2], Bl4[2];
            const uint32_t* pa_ = &As[(kt2 * 8 + wm * 4) * 128 + lane * 4];
            #pragma unroll
            for (int i = 0; i < 4; i++) {
                Afh[i] = *(const uint4*)(pa_ + i * 128);
                Afl[i] = *(const uint4*)(pa_ + 2048 + i * 128);
            }
            const uint32_t* pb_ = &Bs[(kt2 * 8 + wn * 2) * 128 + lane * 4];
            #pragma unroll
            for (int i = 0; i < 2; i++) {
                Bh4[i] = *(const uint4*)(pb_ + i * 128);
                Bl4[i] = *(const uint4*)(pb_ + 2048 + i * 128);
            }
            #pragma unroll
            for (int mt = 0; mt < 4; mt++)
                #pragma unroll
                for (int nt = 0; nt < 4; nt++) {
                    const uint32_t* bh = (const uint32_t*)&Bh4[nt >> 1] + (nt & 1) * 2;
                    const uint32_t* bl = (const uint32_t*)&Bl4[nt >> 1] + (nt & 1) * 2;
                    mma16816(acc[mt][nt], (const uint32_t*)&Afh[mt], bh);
                    mma16816(acc[mt][nt], (const uint32_t*)&Afh[mt], bl);
                    mma16816(acc[mt][nt], (const uint32_t*)&Afl[mt], bh);
                }
        }
    }

    // epilogue
    #pragma unroll
    for (int mt = 0; mt < 4; mt++) {
        #pragma unroll
        for (int nt = 0; nt < 4; nt++) {
            const int m = m0 + wm * 64 + mt * 16 + (lane >> 2);
            const int n = n0 + wn * 32 + nt * 8 + ((lane & 3) << 1);
            float* c = acc[mt][nt];
            const int b = m >> 11, t = m & 2047;
            const int h = n >> 6,  d = n & 63;
            const int bh = b * HH + h;
            if (which < 2) {
                const int i = d >> 1;
                #pragma unroll
                for (int rr = 0; rr < 2; rr++) {
                    const int tt = t + rr * 8;
                    const float2 cs = fc2[tt * 32 + i];
                    float o0 = c[rr*2] * cs.x - c[rr*2+1] * cs.y;
                    float o1 = c[rr*2] * cs.y + c[rr*2+1] * cs.x;
                    uint32_t lo, hi;
                    if (which == 0) {
                        hi = split_pair(o0 * QSCALE, o1 * QSCALE, lo);
                        const size_t qi = qfragidx(bh, tt, i);
                        qfh[qi] = hi; qfl[qi] = lo;
                    } else {
                        hi = split_pair(o0, o1, lo);
                        const size_t ki = kfragidx(bh, tt, i);
                        kfh[ki] = hi; kfl[ki] = lo;
                    }
                }
            } else {
                #pragma unroll
                for (int rr = 0; rr < 2; rr++) {
                    const int tt = t + rr * 8;
                    const int kt3 = tt >> 6, kpp = (tt & 63) >> 1, hf = tt & 1;
                    const int ks3 = kpp >> 3, kk3 = kpp & 7;
                    const int c3 = kk3 & 3, kh3 = kk3 >> 2;
                    #pragma unroll
                    for (int jj = 0; jj < 2; jj++) {
                        const int dd = d + jj;
                        const int ntile = dd >> 3;
                        const int vlane = (dd & 7) * 4 + c3;
                        const int slot = (ks3 * 4 + (ntile >> 1)) * 128 +
                                         vlane * 4 + (ntile & 1) * 2 + kh3;
                        const size_t u32i = (size_t)bh * 65536 + kt3 * 2048 + slot;
                        const float v = c[rr * 2 + jj];
                        __nv_bfloat16 hb = __float2bfloat16_rn(v);
                        __nv_bfloat16 lb = __float2bfloat16_rn(v - __bfloat162float(hb));
                        ((uint16_t*)vfh)[u32i * 2 + hf] = *(uint16_t*)&hb;
                        ((uint16_t*)vfl)[u32i * 2 + hf] = *(uint16_t*)&lb;
                    }
                }
            }
        }
    }
}

// ---------------------------------------------------------------------------
// O-projection GEMM (A-perm x B-perm -> fp32 row-major out). 256 threads.
// ---------------------------------------------------------------------------
__global__ __launch_bounds__(256, 2)
void gemm_o(const uint32_t* __restrict__ Ah, const uint32_t* __restrict__ Al,
            const uint32_t* __restrict__ Wh, const uint32_t* __restrict__ Wl,
            float* __restrict__ C) {
    extern __shared__ __align__(16) uint32_t sm[];

    const int tid  = threadIdx.x;
    const int lane = tid & 31;
    const int w    = tid >> 5;
    const int wm   = w & 1;
    const int wn   = w >> 1;
    const int m0   = blockIdx.y * 128;
    const int n0   = blockIdx.x * 128;
    const size_t abase = ((size_t)blockIdx.y * 32) * 2048;
    const size_t bbase = ((size_t)blockIdx.x * 32) * 2048;
    const uint32_t smaddr = smem_u32(sm);

    float acc[4][4][4];
    #pragma unroll
    for (int i = 0; i < 4; i++)
        #pragma unroll
        for (int j = 0; j < 4; j++)
            #pragma unroll
            for (int r = 0; r < 4; r++) acc[i][j][r] = 0.f;

    auto issue = [&](int st, int kb) {
        const uint32_t dbase = smaddr + (uint32_t)st * 32768u + tid * 32u;
        const size_t ko = (size_t)kb * 2048 + tid * 8;
        CP16(dbase,          Ah + abase + ko);
        CP16(dbase + 16,     Ah + abase + ko + 4);
        CP16(dbase + 8192,   Al + abase + ko);
        CP16(dbase + 8208,   Al + abase + ko + 4);
        CP16(dbase + 16384,  Wh + bbase + ko);
        CP16(dbase + 16400,  Wh + bbase + ko + 4);
        CP16(dbase + 24576,  Wl + bbase + ko);
        CP16(dbase + 24592,  Wl + bbase + ko + 4);
        asm volatile("cp.async.commit_group;" ::: "memory");
    };

    issue(0, 0);

    for (int kb = 0; kb < 32; kb++) {
        asm volatile("cp.async.wait_group 0;" ::: "memory");
        __syncthreads();
        if (kb < 31) issue((kb + 1) & 1, kb + 1);

        const uint32_t* As = sm + (kb & 1) * 8192;
        const uint32_t* Bs = As + 4096;

        #pragma unroll
        for (int kt2 = 0; kt2 < 2; kt2++) {
            uint4 Afh[4], Afl[4];
            uint4 Bh4[2], Bl4[2];
            const uint32_t* pa_ = &As[(kt2 * 8 + wm * 4) * 128 + lane * 4];
            #pragma unroll
            for (int i = 0; i < 4; i++) {
                Afh[i] = *(const uint4*)(pa_ + i * 128);
                Afl[i] = *(const uint4*)(pa_ + 2048 + i * 128);
            }
            const uint32_t* pb_ = &Bs[(kt2 * 8 + wn * 2) * 128 + lane * 4];
            #pragma unroll
            for (int i = 0; i < 2; i++) {
                Bh4[i] = *(const uint4*)(pb_ + i * 128);
                Bl4[i] = *(const uint4*)(pb_ + 2048 + i * 128);
            }
            #pragma unroll
            for (int mt = 0; mt < 4; mt++)
                #pragma unroll
                for (int nt = 0; nt < 4; nt++) {
                    const uint32_t* bh = (const uint32_t*)&Bh4[nt >> 1] + (nt & 1) * 2;
                    const uint32_t* bl = (const uint32_t*)&Bl4[nt >> 1] + (nt & 1) * 2;
                    mma16816(acc[mt][nt], (const uint32_t*)&Afh[mt], bh);
                    mma16816(acc[mt][nt], (const uint32_t*)&Afh[mt], bl);
                    mma16816(acc[mt][nt], (const uint32_t*)&Afl[mt], bh);
                }
        }
    }

    #pragma unroll
    for (int mt = 0; mt < 4; mt++) {
        #pragma unroll
        for (int nt = 0; nt < 4; nt++) {
            const int m = m0 + wm * 64 + mt * 16 + (lane >> 2);
            const int n = n0 + wn * 32 + nt * 8 + ((lane & 3) << 1);
            const float* c = acc[mt][nt];
            *(float2*)&C[(size_t)m * 1024 + n]       = make_float2(c[0], c[1]);
            *(float2*)&C[(size_t)(m + 8) * 1024 + n] = make_float2(c[2], c[3]);
        }
    }
}

// ---------------------------------------------------------------------------
// Tensor-core flash attention (mma.sync, causal, log2-domain softmax).
// 1D grid heavy-first. 2 CTAs/SM. Paired K/V B-frag images (LDS.128 loads).
// smem: [2 stages x 8192 u32][Q-lo 4096 u32] = 80KB.
// ---------------------------------------------------------------------------
__global__ __launch_bounds__(256, 2)
void attn_mma(const uint32_t* __restrict__ qfh, const uint32_t* __restrict__ qfl,
              const uint32_t* __restrict__ kfh, const uint32_t* __restrict__ kfl,
              const uint32_t* __restrict__ vfh, const uint32_t* __restrict__ vfl,
              uint32_t* __restrict__ aoh, uint32_t* __restrict__ aol) {
    extern __shared__ __align__(16) uint32_t sm[];
    const int qi = 15 - (blockIdx.x >> 5);
    const int bh = blockIdx.x & 31;
    const int b  = bh >> 4, hhd = bh & 15;
    const int q0 = qi * 128;
    const int tid = threadIdx.x;
    const int lane = tid & 31;
    const int w = tid >> 5;
    const uint32_t smaddr = smem_u32(sm);
    const size_t hbase = (size_t)bh * 65536;
    uint32_t* qlo_s = sm + 16384;

    uint4 qfh_r[4];
    {
        const size_t qb = hbase + (size_t)qi * 4096;
        #pragma unroll
        for (int ks = 0; ks < 4; ks++) {
            const size_t o = qb + ((w * 4 + ks) * 32 + lane) * 4;
            qfh_r[ks] = *(const uint4*)&qfh[o];
        }
        #pragma unroll
        for (int i = 0; i < 4; i++) {
            const int id = i * 1024 + tid * 4;
            *(uint4*)&qlo_s[id] = *(const uint4*)&qfl[qb + id];
        }
    }
    __syncthreads();

    float oacc[8][4];
    #pragma unroll
    for (int dt = 0; dt < 8; dt++)
        #pragma unroll
        for (int r = 0; r < 4; r++) oacc[dt][r] = 0.f;
    float mr0 = -1e30f, mr1 = -1e30f, lr0 = 0.f, lr1 = 0.f;

    const int r0 = q0 + w * 16;
    const int ntiles = qi * 2 + 2;

    auto issue = [&](int st, int kt) {
        const uint32_t dbase = smaddr + (uint32_t)st * 32768u + tid * 32u;
        const size_t ko = hbase + (size_t)kt * 2048 + tid * 8;
        CP16(dbase,          kfh + ko);
        CP16(dbase + 16,     kfh + ko + 4);
        CP16(dbase + 8192,   kfl + ko);
        CP16(dbase + 8208,   kfl + ko + 4);
        CP16(dbase + 16384,  vfh + ko);
        CP16(dbase + 16400,  vfh + ko + 4);
        CP16(dbase + 24576,  vfl + ko);
        CP16(dbase + 24592,  vfl + ko + 4);
        asm volatile("cp.async.commit_group;" ::: "memory");
    };

    issue(0, 0);

    for (int kt = 0; kt < ntiles; kt++) {
        const int kt0 = kt * 64;
        asm volatile("cp.async.wait_group 0;" ::: "memory");
        __syncthreads();
        if (kt + 1 < ntiles) issue((kt + 1) & 1, kt + 1);

        const uint32_t* S = sm + (kt & 1) * 8192;

        if (kt0 <= r0 + 15) {
            float sacc[8][4];
            #pragma unroll
            for (int nt = 0; nt < 8; nt++)
                #pragma unroll
                for (int r = 0; r < 4; r++) sacc[nt][r] = 0.f;
            #pragma unroll
            for (int ks = 0; ks < 4; ks++) {
                const uint4 qlo = *(const uint4*)&qlo_s[((w * 4 + ks) * 32 + lane) * 4];
                #pragma unroll
                for (int p = 0; p < 4; p++) {
                    const uint4 kh4 = *(const uint4*)&S[(ks * 4 + p) * 128 + lane * 4];
                    const uint4 kl4 = *(const uint4*)&S[2048 + (ks * 4 + p) * 128 + lane * 4];
                    #pragma unroll
                    for (int hh = 0; hh < 2; hh++) {
                        const int nt = p * 2 + hh;
                        const uint32_t* kbh = (const uint32_t*)&kh4 + hh * 2;
                        const uint32_t* kbl = (const uint32_t*)&kl4 + hh * 2;
                        mma16816(sacc[nt], (const uint32_t*)&qfh_r[ks], kbh);
                        mma16816(sacc[nt], (const uint32_t*)&qfh_r[ks], kbl);
                        mma16816(sacc[nt], (const uint32_t*)&qlo, kbh);
                    }
                }
            }
            if (kt0 + 63 > r0) {
                const int colb = kt0 + ((lane & 3) << 1);
                const int rowb = r0 + (lane >> 2);
                #pragma unroll
                for (int nt = 0; nt < 8; nt++) {
                    #pragma unroll
                    for (int r = 0; r < 4; r++) {
                        const int col = colb + nt * 8 + (r & 1);
                        const int row = rowb + ((r >> 1) << 3);
                        if (col > row) sacc[nt][r] = -1e30f;
                    }
                }
            }
            float mx0 = -1e30f, mx1 = -1e30f;
            #pragma unroll
            for (int nt = 0; nt < 8; nt++) {
                mx0 = fmaxf(mx0, fmaxf(sacc[nt][0], sacc[nt][1]));
                mx1 = fmaxf(mx1, fmaxf(sacc[nt][2], sacc[nt][3]));
            }
            mx0 = fmaxf(mx0, __shfl_xor_sync(0xffffffffu, mx0, 1));
            mx0 = fmaxf(mx0, __shfl_xor_sync(0xffffffffu, mx0, 2));
            mx1 = fmaxf(mx1, __shfl_xor_sync(0xffffffffu, mx1, 1));
            mx1 = fmaxf(mx1, __shfl_xor_sync(0xffffffffu, mx1, 2));
            const float mn0 = fmaxf(mr0, mx0);
            const float mn1 = fmaxf(mr1, mx1);
            const float corr0 = ex2f(mr0 - mn0);
            const float corr1 = ex2f(mr1 - mn1);
            mr0 = mn0; mr1 = mn1;
            float s0 = 0.f, s1 = 0.f;
            #pragma unroll
            for (int nt = 0; nt < 8; nt++) {
                sacc[nt][0] = ex2f(sacc[nt][0] - mn0);
                sacc[nt][1] = ex2f(sacc[nt][1] - mn0);
                sacc[nt][2] = ex2f(sacc[nt][2] - mn1);
                sacc[nt][3] = ex2f(sacc[nt][3] - mn1);
                s0 += sacc[nt][0] + sacc[nt][1];
                s1 += sacc[nt][2] + sacc[nt][3];
            }
            lr0 = lr0 * corr0 + s0;
            lr1 = lr1 * corr1 + s1;
            #pragma unroll
            for (int dt = 0; dt < 8; dt++) {
                oacc[dt][0] *= corr0; oacc[dt][1] *= corr0;
                oacc[dt][2] *= corr1; oacc[dt][3] *= corr1;
            }
            uint32_t pah[4][4], pal[4][4];
            #pragma unroll
            for (int ksp = 0; ksp < 4; ksp++) {
                pah[ksp][0] = split_pair(sacc[2*ksp][0],   sacc[2*ksp][1],   pal[ksp][0]);
                pah[ksp][1] = split_pair(sacc[2*ksp][2],   sacc[2*ksp][3],   pal[ksp][1]);
                pah[ksp][2] = split_pair(sacc[2*ksp+1][0], sacc[2*ksp+1][1], pal[ksp][2]);
                pah[ksp][3] = split_pair(sacc[2*ksp+1][2], sacc[2*ksp+1][3], pal[ksp][3]);
            }
            #pragma unroll
            for (int ksp = 0; ksp < 4; ksp++) {
                #pragma unroll
                for (int p = 0; p < 4; p++) {
                    const uint4 vh4 = *(const uint4*)&S[4096 + (ksp * 4 + p) * 128 + lane * 4];
                    const uint4 vl4 = *(const uint4*)&S[6144 + (ksp * 4 + p) * 128 + lane * 4];
                    #pragma unroll
                    for (int hh = 0; hh < 2; hh++) {
                        const int dt = p * 2 + hh;
                        const uint32_t* vbh = (const uint32_t*)&vh4 + hh * 2;
                        const uint32_t* vbl = (const uint32_t*)&vl4 + hh * 2;
                        mma16816(oacc[dt], pah[ksp], vbh);
                        mma16816(oacc[dt], pal[ksp], vbh);
                        mma16816(oacc[dt], pah[ksp], vbl);
                    }
                }
            }
        }
    }

    lr0 += __shfl_xor_sync(0xffffffffu, lr0, 1);
    lr0 += __shfl_xor_sync(0xffffffffu, lr0, 2);
    lr1 += __shfl_xor_sync(0xffffffffu, lr1, 1);
    lr1 += __shfl_xor_sync(0xffffffffu, lr1, 2);
    const float inv0 = 1.f / lr0;
    const float inv1 = 1.f / lr1;
    const int t0 = r0 + (lane >> 2);
    const int t1 = t0 + 8;
    #pragma unroll
    for (int dt = 0; dt < 8; dt++) {
        const int kp = hhd * 32 + dt * 4 + (lane & 3);
        uint32_t lo;
        uint32_t hi = split_pair(oacc[dt][0] * inv0, oacc[dt][1] * inv0, lo);
        const size_t i0 = apermidx(b * TT + t0, kp);
        aoh[i0] = hi; aol[i0] = lo;
        hi = split_pair(oacc[dt][2] * inv1, oacc[dt][3] * inv1, lo);
        const size_t i1 = apermidx(b * TT + t1, kp);
        aoh[i1] = hi; aol[i1] = lo;
    }
}

// ---------------------------------------------------------------------------
extern "C" void kernel_launch(void* const* d_in, const int* in_sizes, int n_in,
                              void* d_out, int out_size) {
    const float* x  = (const float*)d_in[0];
    const float* wq = (const float*)d_in[1];
    const float* wk = (const float*)d_in[2];
    const float* wv = (const float*)d_in[3];
    const float* wo = (const float*)d_in[4];
    const float* fc = (const float*)d_in[5];
    float* out = (float*)d_out;

    uint32_t *qfhp, *qflp, *kfhp, *kflp, *vfhp, *vflp;
    uint32_t *xhp, *xlp, *aohp, *aolp;
    uint32_t *wqhp, *wqlp, *wkhp, *wklp, *wvhp, *wvlp, *wohp, *wolp;
    cudaGetSymbolAddress((void**)&qfhp, g_qfh);
    cudaGetSymbolAddress((void**)&qflp, g_qfl);
    cudaGetSymbolAddress((void**)&kfhp, g_kfh);
    cudaGetSymbolAddress((void**)&kflp, g_kfl);
    cudaGetSymbolAddress((void**)&vfhp, g_vfh);
    cudaGetSymbolAddress((void**)&vflp, g_vfl);
    cudaGetSymbolAddress((void**)&xhp, g_xh);
    cudaGetSymbolAddress((void**)&xlp, g_xl);
    cudaGetSymbolAddress((void**)&aohp, g_aoh);
    cudaGetSymbolAddress((void**)&aolp, g_aol);
    cudaGetSymbolAddress((void**)&wqhp, g_wqh);
    cudaGetSymbolAddress((void**)&wqlp, g_wql);
    cudaGetSymbolAddress((void**)&wkhp, g_wkh);
    cudaGetSymbolAddress((void**)&wklp, g_wkl);
    cudaGetSymbolAddress((void**)&wvhp, g_wvh);
    cudaGetSymbolAddress((void**)&wvlp, g_wvl);
    cudaGetSymbolAddress((void**)&wohp, g_woh);
    cudaGetSymbolAddress((void**)&wolp, g_wol);

    const int DYNSZ  = 65536;
    const int ADYNSZ = 81920;
    cudaFuncSetAttribute(gemm_qkv, cudaFuncAttributeMaxDynamicSharedMemorySize, DYNSZ);
    cudaFuncSetAttribute(gemm_o,   cudaFuncAttributeMaxDynamicSharedMemorySize, DYNSZ);
    cudaFuncSetAttribute(attn_mma, cudaFuncAttributeMaxDynamicSharedMemorySize, ADYNSZ);

    // one right-sized split launch: 8192 x-blocks + 4*2048 weight-blocks
    split_all<<<16384, 256>>>((const float2*)x, (const float2*)wq, (const float2*)wk,
                              (const float2*)wv, (const float2*)wo,
                              xhp, xlp, wqhp, wqlp, wkhp, wklp, wvhp, wvlp,
                              wohp, wolp);

    dim3 qkvgrid(24, M_ROWS / 128);   // (24, 32)
    gemm_qkv<<<qkvgrid, 256, DYNSZ>>>(xhp, xlp, wqhp, wqlp, wkhp, wklp, wvhp, wvlp,
                                      (const float2*)fc, qfhp, qflp, kfhp, kflp,
                                      vfhp, vflp);

    attn_mma<<<512, 256, ADYNSZ>>>(qfhp, qflp, kfhp, kflp, vfhp, vflp, aohp, aolp);

    dim3 ogrid(DD / 128, M_ROWS / 128);
    gemm_o<<<ogrid, 256, DYNSZ>>>(aohp, aolp, wohp, wolp, out);
}